// round 11
// baseline (speedup 1.0000x reference)
#include <cuda_runtime.h>
#include <cuda_bf16.h>
#include <math.h>
#include <stdint.h>

#define NN    50000
#define EE    800000
#define FIN   256
#define ETOT  (EE + NN)
#define NEG_SLOPE 0.2f

// ---------------- scratch (device globals) ----------------------------------
__device__ float g_h1[NN * 256];      // layer-1 linear output [N,4,64]
__device__ float g_as1[NN * 4];
__device__ float g_ad1[NN * 4];
__device__ float g_h2[NN * 32];       // layer-2 linear output
__device__ float g_as2[NN];
__device__ float g_ad2[NN];
// split-bf16 operands for tensor-core GEMMs
__device__ __nv_bfloat16 g_xhi[NN * 256];
__device__ __nv_bfloat16 g_xlo[NN * 256];
__device__ __nv_bfloat16 g_w1hi[256 * 256];   // [n][k] (transposed W1)
__device__ __nv_bfloat16 g_w1lo[256 * 256];
__device__ __nv_bfloat16 g_a2hi[NN * 256];    // relu(agg1+b1) split
__device__ __nv_bfloat16 g_a2lo[NN * 256];
__device__ __nv_bfloat16 g_w2hi[32 * 256];    // [n][k] (transposed W2)
__device__ __nv_bfloat16 g_w2lo[32 * 256];
// CSR (dst-bucketed incoming edges; slot stores src node id)
__device__ int   g_deg[NN];
__device__ int   g_rowstart[NN + 1];
__device__ int   g_col[ETOT];

// ---------------- CSR build --------------------------------------------------
__global__ void k_deg_init(int n) {
    int i = blockIdx.x * blockDim.x + threadIdx.x;
    if (i < n) g_deg[i] = 1;
}
__global__ void k_count(const int* __restrict__ ei, int E) {
    int e = blockIdx.x * blockDim.x + threadIdx.x;
    if (e < E) atomicAdd(&g_deg[ei[E + e]], 1);
}
__global__ void k_scan(int n) {
    __shared__ int sh[1024];
    int tid = threadIdx.x;
    int chunk = (n + 1023) / 1024;
    int beg = tid * chunk;
    int end = min(beg + chunk, n);
    int s = 0;
    for (int i = beg; i < end; i++) s += g_deg[i];
    sh[tid] = s;
    __syncthreads();
    #pragma unroll
    for (int off = 1; off < 1024; off <<= 1) {
        int v = (tid >= off) ? sh[tid - off] : 0;
        __syncthreads();
        sh[tid] += v;
        __syncthreads();
    }
    int run = (tid == 0) ? 0 : sh[tid - 1];
    for (int i = beg; i < end; i++) {
        int c = g_deg[i];
        g_rowstart[i] = run;
        g_deg[i] = run;
        run += c;
    }
    if (tid == 0) g_rowstart[n] = sh[1023];
}
__global__ void k_scatter(const int* __restrict__ ei, int E, int etot) {
    int e = blockIdx.x * blockDim.x + threadIdx.x;
    if (e >= etot) return;
    int s, d;
    if (e < E) { s = ei[e]; d = ei[E + e]; }
    else       { s = d = e - E; }
    int pos = atomicAdd(&g_deg[d], 1);
    g_col[pos] = s;
}

// ---------------- split-bf16 prep -------------------------------------------
__global__ void k_prep_x(const float* __restrict__ x, int total) {
    int i = blockIdx.x * blockDim.x + threadIdx.x;
    if (i >= total) return;
    float f = x[i];
    __nv_bfloat16 hi = __float2bfloat16_rn(f);
    g_xhi[i] = hi;
    g_xlo[i] = __float2bfloat16_rn(f - __bfloat162float(hi));
}
__global__ void k_prep_w(const float* __restrict__ W1) {
    int i = blockIdx.x * blockDim.x + threadIdx.x;
    if (i >= 256 * 256) return;
    int n = i >> 8, k = i & 255;
    float f = W1[k * 256 + n];
    __nv_bfloat16 hi = __float2bfloat16_rn(f);
    g_w1hi[i] = hi;
    g_w1lo[i] = __float2bfloat16_rn(f - __bfloat162float(hi));
}
__global__ void k_prep_w2(const float* __restrict__ W2) {
    int i = blockIdx.x * blockDim.x + threadIdx.x;
    if (i >= 32 * 256) return;
    int n = i >> 8, k = i & 255;
    float f = W2[k * 32 + n];
    __nv_bfloat16 hi = __float2bfloat16_rn(f);
    g_w2hi[i] = hi;
    g_w2lo[i] = __float2bfloat16_rn(f - __bfloat162float(hi));
}

// ---------------- mma.sync helper -------------------------------------------
#define PAD_K 40          // 32 + 8 bf16 padding -> 80-byte rows (16B aligned)
__device__ __forceinline__ void mma16816(float* c, const uint32_t* a, const uint32_t* b) {
    asm volatile(
        "mma.sync.aligned.m16n8k16.row.col.f32.bf16.bf16.f32 "
        "{%0,%1,%2,%3}, {%4,%5,%6,%7}, {%8,%9}, {%0,%1,%2,%3};"
        : "+f"(c[0]), "+f"(c[1]), "+f"(c[2]), "+f"(c[3])
        : "r"(a[0]), "r"(a[1]), "r"(a[2]), "r"(a[3]), "r"(b[0]), "r"(b[1]));
}

// ---------------- GEMM1 via mma.sync bf16 (split hi/lo) ---------------------
// CTA tile 128x128, K chunks of 32; 8 warps (4 M x 2 N), warp tile 32x64.
__global__ void __launch_bounds__(256) k_gemm1_mma(int M) {
    __shared__ __nv_bfloat16 sAhi[128 * PAD_K];
    __shared__ __nv_bfloat16 sAlo[128 * PAD_K];
    __shared__ __nv_bfloat16 sBhi[128 * PAD_K];
    __shared__ __nv_bfloat16 sBlo[128 * PAD_K];

    int tid = threadIdx.x;
    int wid = tid >> 5, lane = tid & 31;
    int wm = wid >> 1, wn = wid & 1;          // 4 x 2 warps
    int row0 = blockIdx.y * 128;
    int col0 = blockIdx.x * 128;

    float acc[2][8][4] = {};

    int lq = lane & 3;
    int lr = lane >> 2;

    for (int kc = 0; kc < 256; kc += 32) {
        #pragma unroll
        for (int i = 0; i < 2; i++) {
            int slot = tid + i * 256;
            int r = slot >> 2, q = slot & 3;
            int gr = row0 + r;
            uint4 vh = make_uint4(0, 0, 0, 0), vl = make_uint4(0, 0, 0, 0);
            if (gr < M) {
                vh = *(const uint4*)(g_xhi + (size_t)gr * 256 + kc + q * 8);
                vl = *(const uint4*)(g_xlo + (size_t)gr * 256 + kc + q * 8);
            }
            *(uint4*)(sAhi + r * PAD_K + q * 8) = vh;
            *(uint4*)(sAlo + r * PAD_K + q * 8) = vl;
        }
        #pragma unroll
        for (int i = 0; i < 2; i++) {
            int slot = tid + i * 256;
            int r = slot >> 2, q = slot & 3;
            int gn = col0 + r;
            *(uint4*)(sBhi + r * PAD_K + q * 8) = *(const uint4*)(g_w1hi + (size_t)gn * 256 + kc + q * 8);
            *(uint4*)(sBlo + r * PAD_K + q * 8) = *(const uint4*)(g_w1lo + (size_t)gn * 256 + kc + q * 8);
        }
        __syncthreads();

        #pragma unroll
        for (int ks = 0; ks < 2; ks++) {
            int kb = ks * 16;
            uint32_t ahi[2][4], alo[2][4], bhi[8][2], blo[8][2];
            #pragma unroll
            for (int mt = 0; mt < 2; mt++) {
                int rbase = wm * 32 + mt * 16;
                const __nv_bfloat16* p0h = sAhi + (rbase + lr) * PAD_K + kb + lq * 2;
                const __nv_bfloat16* p1h = sAhi + (rbase + 8 + lr) * PAD_K + kb + lq * 2;
                const __nv_bfloat16* p0l = sAlo + (rbase + lr) * PAD_K + kb + lq * 2;
                const __nv_bfloat16* p1l = sAlo + (rbase + 8 + lr) * PAD_K + kb + lq * 2;
                ahi[mt][0] = *(const uint32_t*)p0h;
                ahi[mt][1] = *(const uint32_t*)p1h;
                ahi[mt][2] = *(const uint32_t*)(p0h + 8);
                ahi[mt][3] = *(const uint32_t*)(p1h + 8);
                alo[mt][0] = *(const uint32_t*)p0l;
                alo[mt][1] = *(const uint32_t*)p1l;
                alo[mt][2] = *(const uint32_t*)(p0l + 8);
                alo[mt][3] = *(const uint32_t*)(p1l + 8);
            }
            #pragma unroll
            for (int nt = 0; nt < 8; nt++) {
                int nbase = wn * 64 + nt * 8;
                const __nv_bfloat16* ph = sBhi + (nbase + lr) * PAD_K + kb + lq * 2;
                const __nv_bfloat16* pl = sBlo + (nbase + lr) * PAD_K + kb + lq * 2;
                bhi[nt][0] = *(const uint32_t*)ph;
                bhi[nt][1] = *(const uint32_t*)(ph + 8);
                blo[nt][0] = *(const uint32_t*)pl;
                blo[nt][1] = *(const uint32_t*)(pl + 8);
            }
            #pragma unroll
            for (int mt = 0; mt < 2; mt++)
                #pragma unroll
                for (int nt = 0; nt < 8; nt++) {
                    mma16816(acc[mt][nt], ahi[mt], bhi[nt]);
                    mma16816(acc[mt][nt], ahi[mt], blo[nt]);
                    mma16816(acc[mt][nt], alo[mt], bhi[nt]);
                }
        }
        __syncthreads();
    }

    #pragma unroll
    for (int mt = 0; mt < 2; mt++) {
        int r0 = row0 + wm * 32 + mt * 16 + lr;
        #pragma unroll
        for (int nt = 0; nt < 8; nt++) {
            int c = col0 + wn * 64 + nt * 8 + lq * 2;
            if (r0 < M)
                *(float2*)(g_h1 + (size_t)r0 * 256 + c) = make_float2(acc[mt][nt][0], acc[mt][nt][1]);
            if (r0 + 8 < M)
                *(float2*)(g_h1 + (size_t)(r0 + 8) * 256 + c) = make_float2(acc[mt][nt][2], acc[mt][nt][3]);
        }
    }
}

// ---------------- attention dots, layer 1 (warp per node) -------------------
__global__ void k_attn1(const float* __restrict__ att_src, const float* __restrict__ att_dst, int n) {
    int warp = (blockIdx.x * blockDim.x + threadIdx.x) >> 5;
    int lane = threadIdx.x & 31;
    if (warp >= n) return;
    const float4* hr = (const float4*)(g_h1 + (size_t)warp * 256);
    const float4* sa = (const float4*)att_src;
    const float4* da = (const float4*)att_dst;
    float4 v0 = hr[lane], v1 = hr[lane + 32];
    float4 s0 = sa[lane], s1 = sa[lane + 32];
    float4 d0 = da[lane], d1 = da[lane + 32];
    float ps0 = v0.x*s0.x + v0.y*s0.y + v0.z*s0.z + v0.w*s0.w;
    float ps1 = v1.x*s1.x + v1.y*s1.y + v1.z*s1.z + v1.w*s1.w;
    float pd0 = v0.x*d0.x + v0.y*d0.y + v0.z*d0.z + v0.w*d0.w;
    float pd1 = v1.x*d1.x + v1.y*d1.y + v1.z*d1.z + v1.w*d1.w;
    #pragma unroll
    for (int off = 1; off < 16; off <<= 1) {
        ps0 += __shfl_xor_sync(0xffffffffu, ps0, off);
        ps1 += __shfl_xor_sync(0xffffffffu, ps1, off);
        pd0 += __shfl_xor_sync(0xffffffffu, pd0, off);
        pd1 += __shfl_xor_sync(0xffffffffu, pd1, off);
    }
    if (lane == 0)  { g_as1[warp*4+0] = ps0; g_as1[warp*4+2] = ps1;
                      g_ad1[warp*4+0] = pd0; g_ad1[warp*4+2] = pd1; }
    if (lane == 16) { g_as1[warp*4+1] = ps0; g_as1[warp*4+3] = ps1;
                      g_ad1[warp*4+1] = pd0; g_ad1[warp*4+3] = pd1; }
}

// --- fused layer-1 softmax + aggregate + bias + relu -> split bf16 ----------
// block per dst; 256 threads; head = tid/64. Logits recomputed per edge
// (as1 loads are warp-broadcast); sum identical across a head's threads.
__global__ void __launch_bounds__(256) k_agg1(const float* __restrict__ b1) {
    int d = blockIdx.x;
    int tid = threadIdx.x;
    int h = tid >> 6;
    int beg = g_rowstart[d], end = g_rowstart[d + 1];
    float adv = __ldg(&g_ad1[d * 4 + h]);
    float mx = -3.4e38f;
    for (int i = beg; i < end; i++) {
        float v = __ldg(&g_as1[__ldg(&g_col[i]) * 4 + h]) + adv;
        v = (v > 0.f) ? v : NEG_SLOPE * v;
        mx = fmaxf(mx, v);
    }
    float sum = 0.f, acc = 0.f;
    for (int i = beg; i < end; i++) {
        int s = __ldg(&g_col[i]);
        float v = __ldg(&g_as1[s * 4 + h]) + adv;
        v = (v > 0.f) ? v : NEG_SLOPE * v;
        float ex = __expf(v - mx);
        sum += ex;
        acc += __ldg(&g_h1[(size_t)s * 256 + tid]) * ex;
    }
    float val = acc * (1.f / (sum + 1e-16f)) + b1[tid];
    val = fmaxf(val, 0.f);
    __nv_bfloat16 hi = __float2bfloat16_rn(val);
    g_a2hi[(size_t)d * 256 + tid] = hi;
    g_a2lo[(size_t)d * 256 + tid] = __float2bfloat16_rn(val - __bfloat162float(hi));
}

// ------- GEMM2 via mma.sync bf16 (split hi/lo) + fused attn2 dots -----------
// CTA tile 128x32, 8 warps (8 M x 1 N), warp tile 16x32; K chunks of 32.
__global__ void __launch_bounds__(256) k_gemm2_mma(const float* __restrict__ att_src,
                                                   const float* __restrict__ att_dst, int M) {
    __shared__ __nv_bfloat16 sAhi[128 * PAD_K];
    __shared__ __nv_bfloat16 sAlo[128 * PAD_K];
    __shared__ __nv_bfloat16 sBhi[32 * PAD_K];
    __shared__ __nv_bfloat16 sBlo[32 * PAD_K];

    int tid = threadIdx.x;
    int wid = tid >> 5, lane = tid & 31;
    int row0 = blockIdx.x * 128;
    int lq = lane & 3;
    int lr = lane >> 2;

    float acc[4][4] = {};

    for (int kc = 0; kc < 256; kc += 32) {
        #pragma unroll
        for (int i = 0; i < 2; i++) {
            int slot = tid + i * 256;
            int r = slot >> 2, q = slot & 3;
            int gr = row0 + r;
            uint4 vh = make_uint4(0, 0, 0, 0), vl = make_uint4(0, 0, 0, 0);
            if (gr < M) {
                vh = *(const uint4*)(g_a2hi + (size_t)gr * 256 + kc + q * 8);
                vl = *(const uint4*)(g_a2lo + (size_t)gr * 256 + kc + q * 8);
            }
            *(uint4*)(sAhi + r * PAD_K + q * 8) = vh;
            *(uint4*)(sAlo + r * PAD_K + q * 8) = vl;
        }
        if (tid < 128) {
            int r = tid >> 2, q = tid & 3;
            *(uint4*)(sBhi + r * PAD_K + q * 8) = *(const uint4*)(g_w2hi + (size_t)r * 256 + kc + q * 8);
            *(uint4*)(sBlo + r * PAD_K + q * 8) = *(const uint4*)(g_w2lo + (size_t)r * 256 + kc + q * 8);
        }
        __syncthreads();

        #pragma unroll
        for (int ks = 0; ks < 2; ks++) {
            int kb = ks * 16;
            uint32_t ahi[4], alo[4], bhi[4][2], blo[4][2];
            int rbase = wid * 16;
            const __nv_bfloat16* p0h = sAhi + (rbase + lr) * PAD_K + kb + lq * 2;
            const __nv_bfloat16* p1h = sAhi + (rbase + 8 + lr) * PAD_K + kb + lq * 2;
            const __nv_bfloat16* p0l = sAlo + (rbase + lr) * PAD_K + kb + lq * 2;
            const __nv_bfloat16* p1l = sAlo + (rbase + 8 + lr) * PAD_K + kb + lq * 2;
            ahi[0] = *(const uint32_t*)p0h;
            ahi[1] = *(const uint32_t*)p1h;
            ahi[2] = *(const uint32_t*)(p0h + 8);
            ahi[3] = *(const uint32_t*)(p1h + 8);
            alo[0] = *(const uint32_t*)p0l;
            alo[1] = *(const uint32_t*)p1l;
            alo[2] = *(const uint32_t*)(p0l + 8);
            alo[3] = *(const uint32_t*)(p1l + 8);
            #pragma unroll
            for (int nt = 0; nt < 4; nt++) {
                int nbase = nt * 8;
                const __nv_bfloat16* ph = sBhi + (nbase + lr) * PAD_K + kb + lq * 2;
                const __nv_bfloat16* pl = sBlo + (nbase + lr) * PAD_K + kb + lq * 2;
                bhi[nt][0] = *(const uint32_t*)ph;
                bhi[nt][1] = *(const uint32_t*)(ph + 8);
                blo[nt][0] = *(const uint32_t*)pl;
                blo[nt][1] = *(const uint32_t*)(pl + 8);
            }
            #pragma unroll
            for (int nt = 0; nt < 4; nt++) {
                mma16816(acc[nt], ahi, bhi[nt]);
                mma16816(acc[nt], ahi, blo[nt]);
                mma16816(acc[nt], alo, bhi[nt]);
            }
        }
        __syncthreads();
    }

    int r0 = row0 + wid * 16 + lr;
    float ps0 = 0.f, pd0 = 0.f, ps1 = 0.f, pd1 = 0.f;
    #pragma unroll
    for (int nt = 0; nt < 4; nt++) {
        int c = nt * 8 + lq * 2;
        float a0 = __ldg(&att_src[c]), a1 = __ldg(&att_src[c + 1]);
        float d0 = __ldg(&att_dst[c]), d1 = __ldg(&att_dst[c + 1]);
        ps0 += acc[nt][0] * a0 + acc[nt][1] * a1;
        pd0 += acc[nt][0] * d0 + acc[nt][1] * d1;
        ps1 += acc[nt][2] * a0 + acc[nt][3] * a1;
        pd1 += acc[nt][2] * d0 + acc[nt][3] * d1;
        if (r0 < M)
            *(float2*)(g_h2 + (size_t)r0 * 32 + c) = make_float2(acc[nt][0], acc[nt][1]);
        if (r0 + 8 < M)
            *(float2*)(g_h2 + (size_t)(r0 + 8) * 32 + c) = make_float2(acc[nt][2], acc[nt][3]);
    }
    #pragma unroll
    for (int off = 1; off <= 2; off <<= 1) {
        ps0 += __shfl_xor_sync(0xffffffffu, ps0, off);
        pd0 += __shfl_xor_sync(0xffffffffu, pd0, off);
        ps1 += __shfl_xor_sync(0xffffffffu, ps1, off);
        pd1 += __shfl_xor_sync(0xffffffffu, pd1, off);
    }
    if (lq == 0) {
        if (r0 < M)     { g_as2[r0] = ps0;     g_ad2[r0] = pd0; }
        if (r0 + 8 < M) { g_as2[r0 + 8] = ps1; g_ad2[r0 + 8] = pd1; }
    }
}

// ----- fused layer-2 softmax + aggregate + bias + log_softmax (warp/dst) ----
__global__ void __launch_bounds__(256) k_agg2(const float* __restrict__ b2,
                                              float* __restrict__ out, int n) {
    int d = (blockIdx.x * blockDim.x + threadIdx.x) >> 5;
    int lane = threadIdx.x & 31;
    if (d >= n) return;
    int beg = g_rowstart[d], end = g_rowstart[d + 1];
    float adv = __ldg(&g_ad2[d]);
    float mx = -3.4e38f;
    for (int i = beg; i < end; i++) {
        float v = __ldg(&g_as2[__ldg(&g_col[i])]) + adv;
        v = (v > 0.f) ? v : NEG_SLOPE * v;
        mx = fmaxf(mx, v);
    }
    float sum = 0.f, acc = 0.f;
    for (int i = beg; i < end; i++) {
        int s = __ldg(&g_col[i]);
        float v = __ldg(&g_as2[s]) + adv;
        v = (v > 0.f) ? v : NEG_SLOPE * v;
        float ex = __expf(v - mx);
        sum += ex;
        acc += __ldg(&g_h2[(size_t)s * 32 + lane]) * ex;
    }
    float val = acc * (1.f / (sum + 1e-16f)) + b2[lane];
    float m2 = val;
    #pragma unroll
    for (int off = 16; off >= 1; off >>= 1)
        m2 = fmaxf(m2, __shfl_xor_sync(0xffffffffu, m2, off));
    float ex = __expf(val - m2);
    float s2 = ex;
    #pragma unroll
    for (int off = 16; off >= 1; off >>= 1)
        s2 += __shfl_xor_sync(0xffffffffu, s2, off);
    out[(size_t)d * 32 + lane] = val - m2 - logf(s2);
}

// ---------------- launch -----------------------------------------------------
extern "C" void kernel_launch(void* const* d_in, const int* in_sizes, int n_in,
                              void* d_out, int out_size) {
    const float* x    = (const float*)d_in[0];
    const int*   ei   = (const int*)d_in[1];
    const float* W1   = (const float*)d_in[2];
    const float* as1  = (const float*)d_in[3];
    const float* ad1  = (const float*)d_in[4];
    const float* b1   = (const float*)d_in[5];
    const float* W2   = (const float*)d_in[6];
    const float* as2  = (const float*)d_in[7];
    const float* ad2  = (const float*)d_in[8];
    const float* b2   = (const float*)d_in[9];
    float* out = (float*)d_out;

    int n = in_sizes[0] / FIN;
    int E = in_sizes[1] / 2;
    int etot = E + n;

    static cudaStream_t s2 = nullptr;
    static cudaEvent_t evFork = nullptr, evJoin = nullptr;
    if (!s2) {
        cudaStreamCreateWithFlags(&s2, cudaStreamNonBlocking);
        cudaEventCreateWithFlags(&evFork, cudaEventDisableTiming);
        cudaEventCreateWithFlags(&evJoin, cudaEventDisableTiming);
    }

    // fork: CSR build on side stream, overlapped with prep + GEMM1 + attn1
    cudaEventRecord(evFork, 0);
    cudaStreamWaitEvent(s2, evFork, 0);
    k_deg_init<<<(n + 255) / 256, 256, 0, s2>>>(n);
    k_count<<<(E + 255) / 256, 256, 0, s2>>>(ei, E);
    k_scan<<<1, 1024, 0, s2>>>(n);
    k_scatter<<<(etot + 255) / 256, 256, 0, s2>>>(ei, E, etot);
    cudaEventRecord(evJoin, s2);

    // main stream: dense path
    k_prep_x<<<(n * 256 + 255) / 256, 256>>>(x, n * 256);
    k_prep_w<<<(256 * 256 + 255) / 256, 256>>>(W1);
    k_prep_w2<<<(32 * 256 + 255) / 256, 256>>>(W2);

    dim3 g1(2, (n + 127) / 128);
    k_gemm1_mma<<<g1, 256>>>(n);
    k_attn1<<<(n + 7) / 8, 256>>>(as1, ad1, n);

    // join: aggregation needs the CSR
    cudaStreamWaitEvent(0, evJoin, 0);

    k_agg1<<<n, 256>>>(b1);
    k_gemm2_mma<<<(n + 127) / 128, 256>>>(as2, ad2, n);
    k_agg2<<<(n * 32 + 255) / 256, 256>>>(b2, out, n);
}

// round 12
// speedup vs baseline: 1.3867x; 1.3867x over previous
#include <cuda_runtime.h>
#include <cuda_bf16.h>
#include <math.h>
#include <stdint.h>

#define NN    50000
#define EE    800000
#define FIN   256
#define ETOT  (EE + NN)
#define NEG_SLOPE 0.2f

// ---------------- scratch (device globals) ----------------------------------
__device__ float g_h1[NN * 256];      // layer-1 linear output [N,4,64]
__device__ float g_as1[NN * 4];
__device__ float g_ad1[NN * 4];
__device__ float g_h2[NN * 32];       // layer-2 linear output
__device__ float g_as2[NN];
__device__ float g_ad2[NN];
__device__ float g_alpha1[ETOT * 4];  // unnormalized exp weight per CSR slot, head
__device__ float g_rsum1[NN * 4];     // 1/(sum+eps) per (dst, head)
__device__ float g_alpha2[ETOT];
__device__ float g_rsum2[NN];
// split-bf16 operands for tensor-core GEMMs
__device__ __nv_bfloat16 g_xhi[NN * 256];
__device__ __nv_bfloat16 g_xlo[NN * 256];
__device__ __nv_bfloat16 g_w1hi[256 * 256];   // [n][k] (transposed W1)
__device__ __nv_bfloat16 g_w1lo[256 * 256];
__device__ __nv_bfloat16 g_a2hi[NN * 256];    // relu(agg1+b1) split
__device__ __nv_bfloat16 g_a2lo[NN * 256];
__device__ __nv_bfloat16 g_w2hi[32 * 256];    // [n][k] (transposed W2)
__device__ __nv_bfloat16 g_w2lo[32 * 256];
// CSR (dst-bucketed incoming edges; slot stores src node id)
__device__ int   g_deg[NN];
__device__ int   g_rowstart[NN + 1];
__device__ int   g_col[ETOT];

// ---------------- CSR build --------------------------------------------------
__global__ void k_deg_init(int n) {
    int i = blockIdx.x * blockDim.x + threadIdx.x;
    if (i < n) g_deg[i] = 1;
}
__global__ void k_count(const int* __restrict__ ei, int E) {
    int e = blockIdx.x * blockDim.x + threadIdx.x;
    if (e < E) atomicAdd(&g_deg[ei[E + e]], 1);
}
__global__ void k_scan(int n) {
    __shared__ int sh[1024];
    int tid = threadIdx.x;
    int chunk = (n + 1023) / 1024;
    int beg = tid * chunk;
    int end = min(beg + chunk, n);
    int s = 0;
    for (int i = beg; i < end; i++) s += g_deg[i];
    sh[tid] = s;
    __syncthreads();
    #pragma unroll
    for (int off = 1; off < 1024; off <<= 1) {
        int v = (tid >= off) ? sh[tid - off] : 0;
        __syncthreads();
        sh[tid] += v;
        __syncthreads();
    }
    int run = (tid == 0) ? 0 : sh[tid - 1];
    for (int i = beg; i < end; i++) {
        int c = g_deg[i];
        g_rowstart[i] = run;
        g_deg[i] = run;
        run += c;
    }
    if (tid == 0) g_rowstart[n] = sh[1023];
}
__global__ void k_scatter(const int* __restrict__ ei, int E, int etot) {
    int e = blockIdx.x * blockDim.x + threadIdx.x;
    if (e >= etot) return;
    int s, d;
    if (e < E) { s = ei[e]; d = ei[E + e]; }
    else       { s = d = e - E; }
    int pos = atomicAdd(&g_deg[d], 1);
    g_col[pos] = s;
}

// ---------------- split-bf16 prep -------------------------------------------
__global__ void k_prep_x(const float* __restrict__ x, int total) {
    int i = blockIdx.x * blockDim.x + threadIdx.x;
    if (i >= total) return;
    float f = x[i];
    __nv_bfloat16 hi = __float2bfloat16_rn(f);
    g_xhi[i] = hi;
    g_xlo[i] = __float2bfloat16_rn(f - __bfloat162float(hi));
}
__global__ void k_prep_w(const float* __restrict__ W1) {
    int i = blockIdx.x * blockDim.x + threadIdx.x;
    if (i >= 256 * 256) return;
    int n = i >> 8, k = i & 255;
    float f = W1[k * 256 + n];
    __nv_bfloat16 hi = __float2bfloat16_rn(f);
    g_w1hi[i] = hi;
    g_w1lo[i] = __float2bfloat16_rn(f - __bfloat162float(hi));
}
__global__ void k_prep_w2(const float* __restrict__ W2) {
    int i = blockIdx.x * blockDim.x + threadIdx.x;
    if (i >= 32 * 256) return;
    int n = i >> 8, k = i & 255;
    float f = W2[k * 32 + n];
    __nv_bfloat16 hi = __float2bfloat16_rn(f);
    g_w2hi[i] = hi;
    g_w2lo[i] = __float2bfloat16_rn(f - __bfloat162float(hi));
}

// ---------------- mma.sync helper -------------------------------------------
#define PAD_K 40          // 32 + 8 bf16 padding -> 80-byte rows (16B aligned)
__device__ __forceinline__ void mma16816(float* c, const uint32_t* a, const uint32_t* b) {
    asm volatile(
        "mma.sync.aligned.m16n8k16.row.col.f32.bf16.bf16.f32 "
        "{%0,%1,%2,%3}, {%4,%5,%6,%7}, {%8,%9}, {%0,%1,%2,%3};"
        : "+f"(c[0]), "+f"(c[1]), "+f"(c[2]), "+f"(c[3])
        : "r"(a[0]), "r"(a[1]), "r"(a[2]), "r"(a[3]), "r"(b[0]), "r"(b[1]));
}

// ---------------- GEMM1 via mma.sync bf16 (split hi/lo) ---------------------
// CTA tile 128x128, K chunks of 32; 8 warps (4 M x 2 N), warp tile 32x64.
__global__ void __launch_bounds__(256) k_gemm1_mma(int M) {
    __shared__ __nv_bfloat16 sAhi[128 * PAD_K];
    __shared__ __nv_bfloat16 sAlo[128 * PAD_K];
    __shared__ __nv_bfloat16 sBhi[128 * PAD_K];
    __shared__ __nv_bfloat16 sBlo[128 * PAD_K];

    int tid = threadIdx.x;
    int wid = tid >> 5, lane = tid & 31;
    int wm = wid >> 1, wn = wid & 1;          // 4 x 2 warps
    int row0 = blockIdx.y * 128;
    int col0 = blockIdx.x * 128;

    float acc[2][8][4] = {};

    int lq = lane & 3;
    int lr = lane >> 2;

    for (int kc = 0; kc < 256; kc += 32) {
        #pragma unroll
        for (int i = 0; i < 2; i++) {
            int slot = tid + i * 256;
            int r = slot >> 2, q = slot & 3;
            int gr = row0 + r;
            uint4 vh = make_uint4(0, 0, 0, 0), vl = make_uint4(0, 0, 0, 0);
            if (gr < M) {
                vh = *(const uint4*)(g_xhi + (size_t)gr * 256 + kc + q * 8);
                vl = *(const uint4*)(g_xlo + (size_t)gr * 256 + kc + q * 8);
            }
            *(uint4*)(sAhi + r * PAD_K + q * 8) = vh;
            *(uint4*)(sAlo + r * PAD_K + q * 8) = vl;
        }
        #pragma unroll
        for (int i = 0; i < 2; i++) {
            int slot = tid + i * 256;
            int r = slot >> 2, q = slot & 3;
            int gn = col0 + r;
            *(uint4*)(sBhi + r * PAD_K + q * 8) = *(const uint4*)(g_w1hi + (size_t)gn * 256 + kc + q * 8);
            *(uint4*)(sBlo + r * PAD_K + q * 8) = *(const uint4*)(g_w1lo + (size_t)gn * 256 + kc + q * 8);
        }
        __syncthreads();

        #pragma unroll
        for (int ks = 0; ks < 2; ks++) {
            int kb = ks * 16;
            uint32_t ahi[2][4], alo[2][4], bhi[8][2], blo[8][2];
            #pragma unroll
            for (int mt = 0; mt < 2; mt++) {
                int rbase = wm * 32 + mt * 16;
                const __nv_bfloat16* p0h = sAhi + (rbase + lr) * PAD_K + kb + lq * 2;
                const __nv_bfloat16* p1h = sAhi + (rbase + 8 + lr) * PAD_K + kb + lq * 2;
                const __nv_bfloat16* p0l = sAlo + (rbase + lr) * PAD_K + kb + lq * 2;
                const __nv_bfloat16* p1l = sAlo + (rbase + 8 + lr) * PAD_K + kb + lq * 2;
                ahi[mt][0] = *(const uint32_t*)p0h;
                ahi[mt][1] = *(const uint32_t*)p1h;
                ahi[mt][2] = *(const uint32_t*)(p0h + 8);
                ahi[mt][3] = *(const uint32_t*)(p1h + 8);
                alo[mt][0] = *(const uint32_t*)p0l;
                alo[mt][1] = *(const uint32_t*)p1l;
                alo[mt][2] = *(const uint32_t*)(p0l + 8);
                alo[mt][3] = *(const uint32_t*)(p1l + 8);
            }
            #pragma unroll
            for (int nt = 0; nt < 8; nt++) {
                int nbase = wn * 64 + nt * 8;
                const __nv_bfloat16* ph = sBhi + (nbase + lr) * PAD_K + kb + lq * 2;
                const __nv_bfloat16* pl = sBlo + (nbase + lr) * PAD_K + kb + lq * 2;
                bhi[nt][0] = *(const uint32_t*)ph;
                bhi[nt][1] = *(const uint32_t*)(ph + 8);
                blo[nt][0] = *(const uint32_t*)pl;
                blo[nt][1] = *(const uint32_t*)(pl + 8);
            }
            #pragma unroll
            for (int mt = 0; mt < 2; mt++)
                #pragma unroll
                for (int nt = 0; nt < 8; nt++) {
                    mma16816(acc[mt][nt], ahi[mt], bhi[nt]);
                    mma16816(acc[mt][nt], ahi[mt], blo[nt]);
                    mma16816(acc[mt][nt], alo[mt], bhi[nt]);
                }
        }
        __syncthreads();
    }

    #pragma unroll
    for (int mt = 0; mt < 2; mt++) {
        int r0 = row0 + wm * 32 + mt * 16 + lr;
        #pragma unroll
        for (int nt = 0; nt < 8; nt++) {
            int c = col0 + wn * 64 + nt * 8 + lq * 2;
            if (r0 < M)
                *(float2*)(g_h1 + (size_t)r0 * 256 + c) = make_float2(acc[mt][nt][0], acc[mt][nt][1]);
            if (r0 + 8 < M)
                *(float2*)(g_h1 + (size_t)(r0 + 8) * 256 + c) = make_float2(acc[mt][nt][2], acc[mt][nt][3]);
        }
    }
}

// ---------------- attention dots, layer 1 (warp per node) -------------------
__global__ void k_attn1(const float* __restrict__ att_src, const float* __restrict__ att_dst, int n) {
    int warp = (blockIdx.x * blockDim.x + threadIdx.x) >> 5;
    int lane = threadIdx.x & 31;
    if (warp >= n) return;
    const float4* hr = (const float4*)(g_h1 + (size_t)warp * 256);
    const float4* sa = (const float4*)att_src;
    const float4* da = (const float4*)att_dst;
    float4 v0 = hr[lane], v1 = hr[lane + 32];
    float4 s0 = sa[lane], s1 = sa[lane + 32];
    float4 d0 = da[lane], d1 = da[lane + 32];
    float ps0 = v0.x*s0.x + v0.y*s0.y + v0.z*s0.z + v0.w*s0.w;
    float ps1 = v1.x*s1.x + v1.y*s1.y + v1.z*s1.z + v1.w*s1.w;
    float pd0 = v0.x*d0.x + v0.y*d0.y + v0.z*d0.z + v0.w*d0.w;
    float pd1 = v1.x*d1.x + v1.y*d1.y + v1.z*d1.z + v1.w*d1.w;
    #pragma unroll
    for (int off = 1; off < 16; off <<= 1) {
        ps0 += __shfl_xor_sync(0xffffffffu, ps0, off);
        ps1 += __shfl_xor_sync(0xffffffffu, ps1, off);
        pd0 += __shfl_xor_sync(0xffffffffu, pd0, off);
        pd1 += __shfl_xor_sync(0xffffffffu, pd1, off);
    }
    if (lane == 0)  { g_as1[warp*4+0] = ps0; g_as1[warp*4+2] = ps1;
                      g_ad1[warp*4+0] = pd0; g_ad1[warp*4+2] = pd1; }
    if (lane == 16) { g_as1[warp*4+1] = ps0; g_as1[warp*4+3] = ps1;
                      g_ad1[warp*4+1] = pd0; g_ad1[warp*4+3] = pd1; }
}

// ---------------- alpha precompute, layer 1 (thread per dst,head) -----------
__global__ void k_alpha1(int n) {
    int idx = blockIdx.x * blockDim.x + threadIdx.x;
    if (idx >= n * 4) return;
    int d = idx >> 2, h = idx & 3;
    int beg = g_rowstart[d], end = g_rowstart[d + 1];
    float adv = g_ad1[d * 4 + h];
    float mx = -3.4e38f;
    for (int i = beg; i < end; i++) {
        float v = __ldg(&g_as1[__ldg(&g_col[i]) * 4 + h]) + adv;
        v = (v > 0.f) ? v : NEG_SLOPE * v;
        mx = fmaxf(mx, v);
    }
    float sum = 0.f;
    for (int i = beg; i < end; i++) {
        float v = __ldg(&g_as1[__ldg(&g_col[i]) * 4 + h]) + adv;
        v = (v > 0.f) ? v : NEG_SLOPE * v;
        float ex = __expf(v - mx);
        g_alpha1[i * 4 + h] = ex;
        sum += ex;
    }
    g_rsum1[d * 4 + h] = 1.f / (sum + 1e-16f);
}

// --- fused layer-1 aggregate + bias + relu -> split bf16 (block per dst) ----
__global__ void __launch_bounds__(256) k_agg1(const float* __restrict__ b1) {
    int d = blockIdx.x;
    int tid = threadIdx.x;
    int h = tid >> 6;
    int beg = g_rowstart[d], end = g_rowstart[d + 1];
    float acc = 0.f;
    int i = beg;
    for (; i + 1 < end; i += 2) {
        int s0 = __ldg(&g_col[i]);
        int s1 = __ldg(&g_col[i + 1]);
        float w0 = __ldg(&g_alpha1[i * 4 + h]);
        float w1 = __ldg(&g_alpha1[(i + 1) * 4 + h]);
        float v0 = __ldg(&g_h1[(size_t)s0 * 256 + tid]);
        float v1 = __ldg(&g_h1[(size_t)s1 * 256 + tid]);
        acc += v0 * w0 + v1 * w1;
    }
    if (i < end) {
        int s0 = __ldg(&g_col[i]);
        acc += __ldg(&g_h1[(size_t)s0 * 256 + tid]) * __ldg(&g_alpha1[i * 4 + h]);
    }
    float val = acc * g_rsum1[d * 4 + h] + b1[tid];
    val = fmaxf(val, 0.f);
    __nv_bfloat16 hi = __float2bfloat16_rn(val);
    g_a2hi[(size_t)d * 256 + tid] = hi;
    g_a2lo[(size_t)d * 256 + tid] = __float2bfloat16_rn(val - __bfloat162float(hi));
}

// ------- GEMM2 via mma.sync bf16 (split hi/lo) + fused attn2 dots -----------
// CTA tile 128x32, 8 warps (8 M x 1 N), warp tile 16x32; K chunks of 32.
__global__ void __launch_bounds__(256) k_gemm2_mma(const float* __restrict__ att_src,
                                                   const float* __restrict__ att_dst, int M) {
    __shared__ __nv_bfloat16 sAhi[128 * PAD_K];
    __shared__ __nv_bfloat16 sAlo[128 * PAD_K];
    __shared__ __nv_bfloat16 sBhi[32 * PAD_K];
    __shared__ __nv_bfloat16 sBlo[32 * PAD_K];

    int tid = threadIdx.x;
    int wid = tid >> 5, lane = tid & 31;
    int row0 = blockIdx.x * 128;
    int lq = lane & 3;
    int lr = lane >> 2;

    float acc[4][4] = {};

    for (int kc = 0; kc < 256; kc += 32) {
        #pragma unroll
        for (int i = 0; i < 2; i++) {
            int slot = tid + i * 256;
            int r = slot >> 2, q = slot & 3;
            int gr = row0 + r;
            uint4 vh = make_uint4(0, 0, 0, 0), vl = make_uint4(0, 0, 0, 0);
            if (gr < M) {
                vh = *(const uint4*)(g_a2hi + (size_t)gr * 256 + kc + q * 8);
                vl = *(const uint4*)(g_a2lo + (size_t)gr * 256 + kc + q * 8);
            }
            *(uint4*)(sAhi + r * PAD_K + q * 8) = vh;
            *(uint4*)(sAlo + r * PAD_K + q * 8) = vl;
        }
        if (tid < 128) {
            int r = tid >> 2, q = tid & 3;
            *(uint4*)(sBhi + r * PAD_K + q * 8) = *(const uint4*)(g_w2hi + (size_t)r * 256 + kc + q * 8);
            *(uint4*)(sBlo + r * PAD_K + q * 8) = *(const uint4*)(g_w2lo + (size_t)r * 256 + kc + q * 8);
        }
        __syncthreads();

        #pragma unroll
        for (int ks = 0; ks < 2; ks++) {
            int kb = ks * 16;
            uint32_t ahi[4], alo[4], bhi[4][2], blo[4][2];
            int rbase = wid * 16;
            const __nv_bfloat16* p0h = sAhi + (rbase + lr) * PAD_K + kb + lq * 2;
            const __nv_bfloat16* p1h = sAhi + (rbase + 8 + lr) * PAD_K + kb + lq * 2;
            const __nv_bfloat16* p0l = sAlo + (rbase + lr) * PAD_K + kb + lq * 2;
            const __nv_bfloat16* p1l = sAlo + (rbase + 8 + lr) * PAD_K + kb + lq * 2;
            ahi[0] = *(const uint32_t*)p0h;
            ahi[1] = *(const uint32_t*)p1h;
            ahi[2] = *(const uint32_t*)(p0h + 8);
            ahi[3] = *(const uint32_t*)(p1h + 8);
            alo[0] = *(const uint32_t*)p0l;
            alo[1] = *(const uint32_t*)p1l;
            alo[2] = *(const uint32_t*)(p0l + 8);
            alo[3] = *(const uint32_t*)(p1l + 8);
            #pragma unroll
            for (int nt = 0; nt < 4; nt++) {
                int nbase = nt * 8;
                const __nv_bfloat16* ph = sBhi + (nbase + lr) * PAD_K + kb + lq * 2;
                const __nv_bfloat16* pl = sBlo + (nbase + lr) * PAD_K + kb + lq * 2;
                bhi[nt][0] = *(const uint32_t*)ph;
                bhi[nt][1] = *(const uint32_t*)(ph + 8);
                blo[nt][0] = *(const uint32_t*)pl;
                blo[nt][1] = *(const uint32_t*)(pl + 8);
            }
            #pragma unroll
            for (int nt = 0; nt < 4; nt++) {
                mma16816(acc[nt], ahi, bhi[nt]);
                mma16816(acc[nt], ahi, blo[nt]);
                mma16816(acc[nt], alo, bhi[nt]);
            }
        }
        __syncthreads();
    }

    int r0 = row0 + wid * 16 + lr;
    float ps0 = 0.f, pd0 = 0.f, ps1 = 0.f, pd1 = 0.f;
    #pragma unroll
    for (int nt = 0; nt < 4; nt++) {
        int c = nt * 8 + lq * 2;
        float a0 = __ldg(&att_src[c]), a1 = __ldg(&att_src[c + 1]);
        float d0 = __ldg(&att_dst[c]), d1 = __ldg(&att_dst[c + 1]);
        ps0 += acc[nt][0] * a0 + acc[nt][1] * a1;
        pd0 += acc[nt][0] * d0 + acc[nt][1] * d1;
        ps1 += acc[nt][2] * a0 + acc[nt][3] * a1;
        pd1 += acc[nt][2] * d0 + acc[nt][3] * d1;
        if (r0 < M)
            *(float2*)(g_h2 + (size_t)r0 * 32 + c) = make_float2(acc[nt][0], acc[nt][1]);
        if (r0 + 8 < M)
            *(float2*)(g_h2 + (size_t)(r0 + 8) * 32 + c) = make_float2(acc[nt][2], acc[nt][3]);
    }
    #pragma unroll
    for (int off = 1; off <= 2; off <<= 1) {
        ps0 += __shfl_xor_sync(0xffffffffu, ps0, off);
        pd0 += __shfl_xor_sync(0xffffffffu, pd0, off);
        ps1 += __shfl_xor_sync(0xffffffffu, ps1, off);
        pd1 += __shfl_xor_sync(0xffffffffu, pd1, off);
    }
    if (lq == 0) {
        if (r0 < M)     { g_as2[r0] = ps0;     g_ad2[r0] = pd0; }
        if (r0 + 8 < M) { g_as2[r0 + 8] = ps1; g_ad2[r0 + 8] = pd1; }
    }
}

// ---------------- alpha precompute, layer 2 (thread per dst) ----------------
__global__ void k_alpha2(int n) {
    int d = blockIdx.x * blockDim.x + threadIdx.x;
    if (d >= n) return;
    int beg = g_rowstart[d], end = g_rowstart[d + 1];
    float adv = g_ad2[d];
    float mx = -3.4e38f;
    for (int i = beg; i < end; i++) {
        float v = __ldg(&g_as2[__ldg(&g_col[i])]) + adv;
        v = (v > 0.f) ? v : NEG_SLOPE * v;
        mx = fmaxf(mx, v);
    }
    float sum = 0.f;
    for (int i = beg; i < end; i++) {
        float v = __ldg(&g_as2[__ldg(&g_col[i])]) + adv;
        v = (v > 0.f) ? v : NEG_SLOPE * v;
        float ex = __expf(v - mx);
        g_alpha2[i] = ex;
        sum += ex;
    }
    g_rsum2[d] = 1.f / (sum + 1e-16f);
}

// ----- fused layer-2 aggregate + bias + log_softmax (warp per dst) ----------
__global__ void __launch_bounds__(256) k_agg2(const float* __restrict__ b2,
                                              float* __restrict__ out, int n) {
    int d = (blockIdx.x * blockDim.x + threadIdx.x) >> 5;
    int lane = threadIdx.x & 31;
    if (d >= n) return;
    int beg = g_rowstart[d], end = g_rowstart[d + 1];
    float acc = 0.f;
    int i = beg;
    for (; i + 1 < end; i += 2) {
        int s0 = __ldg(&g_col[i]);
        int s1 = __ldg(&g_col[i + 1]);
        float w0 = __ldg(&g_alpha2[i]);
        float w1 = __ldg(&g_alpha2[i + 1]);
        acc += __ldg(&g_h2[(size_t)s0 * 32 + lane]) * w0
             + __ldg(&g_h2[(size_t)s1 * 32 + lane]) * w1;
    }
    if (i < end) {
        int s0 = __ldg(&g_col[i]);
        acc += __ldg(&g_h2[(size_t)s0 * 32 + lane]) * __ldg(&g_alpha2[i]);
    }
    float val = acc * g_rsum2[d] + b2[lane];
    float m2 = val;
    #pragma unroll
    for (int off = 16; off >= 1; off >>= 1)
        m2 = fmaxf(m2, __shfl_xor_sync(0xffffffffu, m2, off));
    float ex = __expf(val - m2);
    float s2 = ex;
    #pragma unroll
    for (int off = 16; off >= 1; off >>= 1)
        s2 += __shfl_xor_sync(0xffffffffu, s2, off);
    out[(size_t)d * 32 + lane] = val - m2 - logf(s2);
}

// ---------------- launch -----------------------------------------------------
extern "C" void kernel_launch(void* const* d_in, const int* in_sizes, int n_in,
                              void* d_out, int out_size) {
    const float* x    = (const float*)d_in[0];
    const int*   ei   = (const int*)d_in[1];
    const float* W1   = (const float*)d_in[2];
    const float* as1  = (const float*)d_in[3];
    const float* ad1  = (const float*)d_in[4];
    const float* b1   = (const float*)d_in[5];
    const float* W2   = (const float*)d_in[6];
    const float* as2  = (const float*)d_in[7];
    const float* ad2  = (const float*)d_in[8];
    const float* b2   = (const float*)d_in[9];
    float* out = (float*)d_out;

    int n = in_sizes[0] / FIN;
    int E = in_sizes[1] / 2;
    int etot = E + n;

    static cudaStream_t s2 = nullptr;
    static cudaEvent_t evFork = nullptr, evJoin = nullptr;
    if (!s2) {
        cudaStreamCreateWithFlags(&s2, cudaStreamNonBlocking);
        cudaEventCreateWithFlags(&evFork, cudaEventDisableTiming);
        cudaEventCreateWithFlags(&evJoin, cudaEventDisableTiming);
    }

    // fork: CSR build on side stream, overlapped with prep + GEMM1 + attn1
    cudaEventRecord(evFork, 0);
    cudaStreamWaitEvent(s2, evFork, 0);
    k_deg_init<<<(n + 255) / 256, 256, 0, s2>>>(n);
    k_count<<<(E + 255) / 256, 256, 0, s2>>>(ei, E);
    k_scan<<<1, 1024, 0, s2>>>(n);
    k_scatter<<<(etot + 255) / 256, 256, 0, s2>>>(ei, E, etot);
    cudaEventRecord(evJoin, s2);

    // main stream: dense path
    k_prep_x<<<(n * 256 + 255) / 256, 256>>>(x, n * 256);
    k_prep_w<<<(256 * 256 + 255) / 256, 256>>>(W1);
    k_prep_w2<<<(32 * 256 + 255) / 256, 256>>>(W2);

    dim3 g1(2, (n + 127) / 128);
    k_gemm1_mma<<<g1, 256>>>(n);
    k_attn1<<<(n + 7) / 8, 256>>>(as1, ad1, n);

    // join: alpha/agg need the CSR
    cudaStreamWaitEvent(0, evJoin, 0);

    k_alpha1<<<(n * 4 + 255) / 256, 256>>>(n);
    k_agg1<<<n, 256>>>(b1);

    k_gemm2_mma<<<(n + 127) / 128, 256>>>(as2, ad2, n);
    k_alpha2<<<(n + 255) / 256, 256>>>(n);
    k_agg2<<<(n * 32 + 255) / 256, 256>>>(b2, out, n);
}

// round 13
// speedup vs baseline: 1.4037x; 1.0122x over previous
#include <cuda_runtime.h>
#include <cuda_bf16.h>
#include <math.h>
#include <stdint.h>

#define NN    50000
#define EE    800000
#define FIN   256
#define ETOT  (EE + NN)
#define NEG_SLOPE 0.2f

// ---------------- scratch (device globals) ----------------------------------
__device__ float g_h1[NN * 256];      // layer-1 linear output [N,4,64]
__device__ float g_as1[NN * 4];
__device__ float g_ad1[NN * 4];
__device__ float g_h2[NN * 32];       // layer-2 linear output
__device__ float g_as2[NN];
__device__ float g_ad2[NN];
__device__ float g_alpha1[ETOT * 4];  // unnormalized exp weight per CSR slot, head
__device__ float g_rsum1[NN * 4];     // 1/(sum+eps) per (dst, head)
// split-bf16 operands for tensor-core GEMMs
__device__ __nv_bfloat16 g_xhi[NN * 256];
__device__ __nv_bfloat16 g_xlo[NN * 256];
__device__ __nv_bfloat16 g_w1hi[256 * 256];   // [n][k] (transposed W1)
__device__ __nv_bfloat16 g_w1lo[256 * 256];
__device__ __nv_bfloat16 g_a2hi[NN * 256];    // relu(agg1+b1) split
__device__ __nv_bfloat16 g_a2lo[NN * 256];
__device__ __nv_bfloat16 g_w2hi[32 * 256];    // [n][k] (transposed W2)
__device__ __nv_bfloat16 g_w2lo[32 * 256];
// CSR (dst-bucketed incoming edges; slot stores src node id)
__device__ int   g_deg[NN];
__device__ int   g_rowstart[NN + 1];
__device__ int   g_col[ETOT];

// ---------------- CSR build --------------------------------------------------
__global__ void k_deg_init(int n) {
    int i = blockIdx.x * blockDim.x + threadIdx.x;
    if (i < n) g_deg[i] = 1;
}
__global__ void k_count(const int* __restrict__ ei, int E) {
    int e = blockIdx.x * blockDim.x + threadIdx.x;
    if (e < E) atomicAdd(&g_deg[ei[E + e]], 1);
}
__global__ void k_scan(int n) {
    __shared__ int sh[1024];
    int tid = threadIdx.x;
    int chunk = (n + 1023) / 1024;
    int beg = tid * chunk;
    int end = min(beg + chunk, n);
    int s = 0;
    for (int i = beg; i < end; i++) s += g_deg[i];
    sh[tid] = s;
    __syncthreads();
    #pragma unroll
    for (int off = 1; off < 1024; off <<= 1) {
        int v = (tid >= off) ? sh[tid - off] : 0;
        __syncthreads();
        sh[tid] += v;
        __syncthreads();
    }
    int run = (tid == 0) ? 0 : sh[tid - 1];
    for (int i = beg; i < end; i++) {
        int c = g_deg[i];
        g_rowstart[i] = run;
        g_deg[i] = run;
        run += c;
    }
    if (tid == 0) g_rowstart[n] = sh[1023];
}
__global__ void k_scatter(const int* __restrict__ ei, int E, int etot) {
    int e = blockIdx.x * blockDim.x + threadIdx.x;
    if (e >= etot) return;
    int s, d;
    if (e < E) { s = ei[e]; d = ei[E + e]; }
    else       { s = d = e - E; }
    int pos = atomicAdd(&g_deg[d], 1);
    g_col[pos] = s;
}

// ---------------- split-bf16 prep -------------------------------------------
__global__ void k_prep_x(const float* __restrict__ x, int total) {
    int i = blockIdx.x * blockDim.x + threadIdx.x;
    if (i >= total) return;
    float f = x[i];
    __nv_bfloat16 hi = __float2bfloat16_rn(f);
    g_xhi[i] = hi;
    g_xlo[i] = __float2bfloat16_rn(f - __bfloat162float(hi));
}
__global__ void k_prep_w(const float* __restrict__ W1) {
    int i = blockIdx.x * blockDim.x + threadIdx.x;
    if (i >= 256 * 256) return;
    int n = i >> 8, k = i & 255;
    float f = W1[k * 256 + n];
    __nv_bfloat16 hi = __float2bfloat16_rn(f);
    g_w1hi[i] = hi;
    g_w1lo[i] = __float2bfloat16_rn(f - __bfloat162float(hi));
}
__global__ void k_prep_w2(const float* __restrict__ W2) {
    int i = blockIdx.x * blockDim.x + threadIdx.x;
    if (i >= 32 * 256) return;
    int n = i >> 8, k = i & 255;
    float f = W2[k * 32 + n];
    __nv_bfloat16 hi = __float2bfloat16_rn(f);
    g_w2hi[i] = hi;
    g_w2lo[i] = __float2bfloat16_rn(f - __bfloat162float(hi));
}

// ---------------- mma.sync helper -------------------------------------------
#define PAD_K 40          // 32 + 8 bf16 padding -> 80-byte rows (16B aligned)
__device__ __forceinline__ void mma16816(float* c, const uint32_t* a, const uint32_t* b) {
    asm volatile(
        "mma.sync.aligned.m16n8k16.row.col.f32.bf16.bf16.f32 "
        "{%0,%1,%2,%3}, {%4,%5,%6,%7}, {%8,%9}, {%0,%1,%2,%3};"
        : "+f"(c[0]), "+f"(c[1]), "+f"(c[2]), "+f"(c[3])
        : "r"(a[0]), "r"(a[1]), "r"(a[2]), "r"(a[3]), "r"(b[0]), "r"(b[1]));
}

// ------- GEMM1 via mma.sync bf16 (split hi/lo) + fused attn1 dots -----------
// CTA tile 128x128, K chunks of 32; 8 warps (4 M x 2 N), warp tile 32x64.
// Each warp's 64 columns = exactly one head -> per-row attention dots reduce
// across the 4-lane quad and write g_as1/g_ad1 directly (disjoint per CTA).
__global__ void __launch_bounds__(256) k_gemm1_mma(const float* __restrict__ att_src,
                                                   const float* __restrict__ att_dst, int M) {
    __shared__ __nv_bfloat16 sAhi[128 * PAD_K];
    __shared__ __nv_bfloat16 sAlo[128 * PAD_K];
    __shared__ __nv_bfloat16 sBhi[128 * PAD_K];
    __shared__ __nv_bfloat16 sBlo[128 * PAD_K];

    int tid = threadIdx.x;
    int wid = tid >> 5, lane = tid & 31;
    int wm = wid >> 1, wn = wid & 1;          // 4 x 2 warps
    int row0 = blockIdx.y * 128;
    int col0 = blockIdx.x * 128;

    float acc[2][8][4] = {};

    int lq = lane & 3;
    int lr = lane >> 2;

    for (int kc = 0; kc < 256; kc += 32) {
        #pragma unroll
        for (int i = 0; i < 2; i++) {
            int slot = tid + i * 256;
            int r = slot >> 2, q = slot & 3;
            int gr = row0 + r;
            uint4 vh = make_uint4(0, 0, 0, 0), vl = make_uint4(0, 0, 0, 0);
            if (gr < M) {
                vh = *(const uint4*)(g_xhi + (size_t)gr * 256 + kc + q * 8);
                vl = *(const uint4*)(g_xlo + (size_t)gr * 256 + kc + q * 8);
            }
            *(uint4*)(sAhi + r * PAD_K + q * 8) = vh;
            *(uint4*)(sAlo + r * PAD_K + q * 8) = vl;
        }
        #pragma unroll
        for (int i = 0; i < 2; i++) {
            int slot = tid + i * 256;
            int r = slot >> 2, q = slot & 3;
            int gn = col0 + r;
            *(uint4*)(sBhi + r * PAD_K + q * 8) = *(const uint4*)(g_w1hi + (size_t)gn * 256 + kc + q * 8);
            *(uint4*)(sBlo + r * PAD_K + q * 8) = *(const uint4*)(g_w1lo + (size_t)gn * 256 + kc + q * 8);
        }
        __syncthreads();

        #pragma unroll
        for (int ks = 0; ks < 2; ks++) {
            int kb = ks * 16;
            uint32_t ahi[2][4], alo[2][4], bhi[8][2], blo[8][2];
            #pragma unroll
            for (int mt = 0; mt < 2; mt++) {
                int rbase = wm * 32 + mt * 16;
                const __nv_bfloat16* p0h = sAhi + (rbase + lr) * PAD_K + kb + lq * 2;
                const __nv_bfloat16* p1h = sAhi + (rbase + 8 + lr) * PAD_K + kb + lq * 2;
                const __nv_bfloat16* p0l = sAlo + (rbase + lr) * PAD_K + kb + lq * 2;
                const __nv_bfloat16* p1l = sAlo + (rbase + 8 + lr) * PAD_K + kb + lq * 2;
                ahi[mt][0] = *(const uint32_t*)p0h;
                ahi[mt][1] = *(const uint32_t*)p1h;
                ahi[mt][2] = *(const uint32_t*)(p0h + 8);
                ahi[mt][3] = *(const uint32_t*)(p1h + 8);
                alo[mt][0] = *(const uint32_t*)p0l;
                alo[mt][1] = *(const uint32_t*)p1l;
                alo[mt][2] = *(const uint32_t*)(p0l + 8);
                alo[mt][3] = *(const uint32_t*)(p1l + 8);
            }
            #pragma unroll
            for (int nt = 0; nt < 8; nt++) {
                int nbase = wn * 64 + nt * 8;
                const __nv_bfloat16* ph = sBhi + (nbase + lr) * PAD_K + kb + lq * 2;
                const __nv_bfloat16* pl = sBlo + (nbase + lr) * PAD_K + kb + lq * 2;
                bhi[nt][0] = *(const uint32_t*)ph;
                bhi[nt][1] = *(const uint32_t*)(ph + 8);
                blo[nt][0] = *(const uint32_t*)pl;
                blo[nt][1] = *(const uint32_t*)(pl + 8);
            }
            #pragma unroll
            for (int mt = 0; mt < 2; mt++)
                #pragma unroll
                for (int nt = 0; nt < 8; nt++) {
                    mma16816(acc[mt][nt], ahi[mt], bhi[nt]);
                    mma16816(acc[mt][nt], ahi[mt], blo[nt]);
                    mma16816(acc[mt][nt], alo[mt], bhi[nt]);
                }
        }
        __syncthreads();
    }

    int h = (col0 >> 6) + wn;   // this warp's head
    #pragma unroll
    for (int mt = 0; mt < 2; mt++) {
        int r0 = row0 + wm * 32 + mt * 16 + lr;
        float ps0 = 0.f, pd0 = 0.f, ps1 = 0.f, pd1 = 0.f;
        #pragma unroll
        for (int nt = 0; nt < 8; nt++) {
            int c = col0 + wn * 64 + nt * 8 + lq * 2;
            int ci = h * 64 + nt * 8 + lq * 2;      // index into flat [4][64] att vec
            float a0 = __ldg(&att_src[ci]), a1 = __ldg(&att_src[ci + 1]);
            float d0 = __ldg(&att_dst[ci]), d1 = __ldg(&att_dst[ci + 1]);
            ps0 += acc[mt][nt][0] * a0 + acc[mt][nt][1] * a1;
            pd0 += acc[mt][nt][0] * d0 + acc[mt][nt][1] * d1;
            ps1 += acc[mt][nt][2] * a0 + acc[mt][nt][3] * a1;
            pd1 += acc[mt][nt][2] * d0 + acc[mt][nt][3] * d1;
            if (r0 < M)
                *(float2*)(g_h1 + (size_t)r0 * 256 + c) = make_float2(acc[mt][nt][0], acc[mt][nt][1]);
            if (r0 + 8 < M)
                *(float2*)(g_h1 + (size_t)(r0 + 8) * 256 + c) = make_float2(acc[mt][nt][2], acc[mt][nt][3]);
        }
        #pragma unroll
        for (int off = 1; off <= 2; off <<= 1) {
            ps0 += __shfl_xor_sync(0xffffffffu, ps0, off);
            pd0 += __shfl_xor_sync(0xffffffffu, pd0, off);
            ps1 += __shfl_xor_sync(0xffffffffu, ps1, off);
            pd1 += __shfl_xor_sync(0xffffffffu, pd1, off);
        }
        if (lq == 0) {
            if (r0 < M)     { g_as1[r0 * 4 + h] = ps0;       g_ad1[r0 * 4 + h] = pd0; }
            if (r0 + 8 < M) { g_as1[(r0 + 8) * 4 + h] = ps1; g_ad1[(r0 + 8) * 4 + h] = pd1; }
        }
    }
}

// ------ alpha precompute, layer 1 (thread per dst; all 4 heads, float4) -----
__global__ void k_alpha1(int n) {
    int d = blockIdx.x * blockDim.x + threadIdx.x;
    if (d >= n) return;
    int beg = g_rowstart[d], end = g_rowstart[d + 1];
    float4 adv = *(const float4*)&g_ad1[d * 4];
    float4 mx = make_float4(-3.4e38f, -3.4e38f, -3.4e38f, -3.4e38f);
    for (int i = beg; i < end; i++) {
        float4 a = __ldg((const float4*)&g_as1[__ldg(&g_col[i]) * 4]);
        float vx = a.x + adv.x, vy = a.y + adv.y, vz = a.z + adv.z, vw = a.w + adv.w;
        vx = (vx > 0.f) ? vx : NEG_SLOPE * vx;
        vy = (vy > 0.f) ? vy : NEG_SLOPE * vy;
        vz = (vz > 0.f) ? vz : NEG_SLOPE * vz;
        vw = (vw > 0.f) ? vw : NEG_SLOPE * vw;
        mx.x = fmaxf(mx.x, vx); mx.y = fmaxf(mx.y, vy);
        mx.z = fmaxf(mx.z, vz); mx.w = fmaxf(mx.w, vw);
    }
    float4 sum = make_float4(0.f, 0.f, 0.f, 0.f);
    for (int i = beg; i < end; i++) {
        float4 a = __ldg((const float4*)&g_as1[__ldg(&g_col[i]) * 4]);
        float vx = a.x + adv.x, vy = a.y + adv.y, vz = a.z + adv.z, vw = a.w + adv.w;
        vx = (vx > 0.f) ? vx : NEG_SLOPE * vx;
        vy = (vy > 0.f) ? vy : NEG_SLOPE * vy;
        vz = (vz > 0.f) ? vz : NEG_SLOPE * vz;
        vw = (vw > 0.f) ? vw : NEG_SLOPE * vw;
        float4 ex = make_float4(__expf(vx - mx.x), __expf(vy - mx.y),
                                __expf(vz - mx.z), __expf(vw - mx.w));
        *(float4*)&g_alpha1[i * 4] = ex;
        sum.x += ex.x; sum.y += ex.y; sum.z += ex.z; sum.w += ex.w;
    }
    *(float4*)&g_rsum1[d * 4] = make_float4(
        1.f / (sum.x + 1e-16f), 1.f / (sum.y + 1e-16f),
        1.f / (sum.z + 1e-16f), 1.f / (sum.w + 1e-16f));
}

// --- fused layer-1 aggregate + bias + relu -> split bf16 (block per dst) ----
__global__ void __launch_bounds__(256) k_agg1(const float* __restrict__ b1) {
    int d = blockIdx.x;
    int tid = threadIdx.x;
    int h = tid >> 6;
    int beg = g_rowstart[d], end = g_rowstart[d + 1];
    float acc = 0.f;
    int i = beg;
    for (; i + 1 < end; i += 2) {
        int s0 = __ldg(&g_col[i]);
        int s1 = __ldg(&g_col[i + 1]);
        float w0 = __ldg(&g_alpha1[i * 4 + h]);
        float w1 = __ldg(&g_alpha1[(i + 1) * 4 + h]);
        float v0 = __ldg(&g_h1[(size_t)s0 * 256 + tid]);
        float v1 = __ldg(&g_h1[(size_t)s1 * 256 + tid]);
        acc += v0 * w0 + v1 * w1;
    }
    if (i < end) {
        int s0 = __ldg(&g_col[i]);
        acc += __ldg(&g_h1[(size_t)s0 * 256 + tid]) * __ldg(&g_alpha1[i * 4 + h]);
    }
    float val = acc * g_rsum1[d * 4 + h] + b1[tid];
    val = fmaxf(val, 0.f);
    __nv_bfloat16 hi = __float2bfloat16_rn(val);
    g_a2hi[(size_t)d * 256 + tid] = hi;
    g_a2lo[(size_t)d * 256 + tid] = __float2bfloat16_rn(val - __bfloat162float(hi));
}

// ------- GEMM2 via mma.sync bf16 (split hi/lo) + fused attn2 dots -----------
// CTA tile 128x32, 8 warps (8 M x 1 N), warp tile 16x32; K chunks of 32.
__global__ void __launch_bounds__(256) k_gemm2_mma(const float* __restrict__ att_src,
                                                   const float* __restrict__ att_dst, int M) {
    __shared__ __nv_bfloat16 sAhi[128 * PAD_K];
    __shared__ __nv_bfloat16 sAlo[128 * PAD_K];
    __shared__ __nv_bfloat16 sBhi[32 * PAD_K];
    __shared__ __nv_bfloat16 sBlo[32 * PAD_K];

    int tid = threadIdx.x;
    int wid = tid >> 5, lane = tid & 31;
    int row0 = blockIdx.x * 128;
    int lq = lane & 3;
    int lr = lane >> 2;

    float acc[4][4] = {};

    for (int kc = 0; kc < 256; kc += 32) {
        #pragma unroll
        for (int i = 0; i < 2; i++) {
            int slot = tid + i * 256;
            int r = slot >> 2, q = slot & 3;
            int gr = row0 + r;
            uint4 vh = make_uint4(0, 0, 0, 0), vl = make_uint4(0, 0, 0, 0);
            if (gr < M) {
                vh = *(const uint4*)(g_a2hi + (size_t)gr * 256 + kc + q * 8);
                vl = *(const uint4*)(g_a2lo + (size_t)gr * 256 + kc + q * 8);
            }
            *(uint4*)(sAhi + r * PAD_K + q * 8) = vh;
            *(uint4*)(sAlo + r * PAD_K + q * 8) = vl;
        }
        if (tid < 128) {
            int r = tid >> 2, q = tid & 3;
            *(uint4*)(sBhi + r * PAD_K + q * 8) = *(const uint4*)(g_w2hi + (size_t)r * 256 + kc + q * 8);
            *(uint4*)(sBlo + r * PAD_K + q * 8) = *(const uint4*)(g_w2lo + (size_t)r * 256 + kc + q * 8);
        }
        __syncthreads();

        #pragma unroll
        for (int ks = 0; ks < 2; ks++) {
            int kb = ks * 16;
            uint32_t ahi[4], alo[4], bhi[4][2], blo[4][2];
            int rbase = wid * 16;
            const __nv_bfloat16* p0h = sAhi + (rbase + lr) * PAD_K + kb + lq * 2;
            const __nv_bfloat16* p1h = sAhi + (rbase + 8 + lr) * PAD_K + kb + lq * 2;
            const __nv_bfloat16* p0l = sAlo + (rbase + lr) * PAD_K + kb + lq * 2;
            const __nv_bfloat16* p1l = sAlo + (rbase + 8 + lr) * PAD_K + kb + lq * 2;
            ahi[0] = *(const uint32_t*)p0h;
            ahi[1] = *(const uint32_t*)p1h;
            ahi[2] = *(const uint32_t*)(p0h + 8);
            ahi[3] = *(const uint32_t*)(p1h + 8);
            alo[0] = *(const uint32_t*)p0l;
            alo[1] = *(const uint32_t*)p1l;
            alo[2] = *(const uint32_t*)(p0l + 8);
            alo[3] = *(const uint32_t*)(p1l + 8);
            #pragma unroll
            for (int nt = 0; nt < 4; nt++) {
                int nbase = nt * 8;
                const __nv_bfloat16* ph = sBhi + (nbase + lr) * PAD_K + kb + lq * 2;
                const __nv_bfloat16* pl = sBlo + (nbase + lr) * PAD_K + kb + lq * 2;
                bhi[nt][0] = *(const uint32_t*)ph;
                bhi[nt][1] = *(const uint32_t*)(ph + 8);
                blo[nt][0] = *(const uint32_t*)pl;
                blo[nt][1] = *(const uint32_t*)(pl + 8);
            }
            #pragma unroll
            for (int nt = 0; nt < 4; nt++) {
                mma16816(acc[nt], ahi, bhi[nt]);
                mma16816(acc[nt], ahi, blo[nt]);
                mma16816(acc[nt], alo, bhi[nt]);
            }
        }
        __syncthreads();
    }

    int r0 = row0 + wid * 16 + lr;
    float ps0 = 0.f, pd0 = 0.f, ps1 = 0.f, pd1 = 0.f;
    #pragma unroll
    for (int nt = 0; nt < 4; nt++) {
        int c = nt * 8 + lq * 2;
        float a0 = __ldg(&att_src[c]), a1 = __ldg(&att_src[c + 1]);
        float d0 = __ldg(&att_dst[c]), d1 = __ldg(&att_dst[c + 1]);
        ps0 += acc[nt][0] * a0 + acc[nt][1] * a1;
        pd0 += acc[nt][0] * d0 + acc[nt][1] * d1;
        ps1 += acc[nt][2] * a0 + acc[nt][3] * a1;
        pd1 += acc[nt][2] * d0 + acc[nt][3] * d1;
        if (r0 < M)
            *(float2*)(g_h2 + (size_t)r0 * 32 + c) = make_float2(acc[nt][0], acc[nt][1]);
        if (r0 + 8 < M)
            *(float2*)(g_h2 + (size_t)(r0 + 8) * 32 + c) = make_float2(acc[nt][2], acc[nt][3]);
    }
    #pragma unroll
    for (int off = 1; off <= 2; off <<= 1) {
        ps0 += __shfl_xor_sync(0xffffffffu, ps0, off);
        pd0 += __shfl_xor_sync(0xffffffffu, pd0, off);
        ps1 += __shfl_xor_sync(0xffffffffu, ps1, off);
        pd1 += __shfl_xor_sync(0xffffffffu, pd1, off);
    }
    if (lq == 0) {
        if (r0 < M)     { g_as2[r0] = ps0;     g_ad2[r0] = pd0; }
        if (r0 + 8 < M) { g_as2[r0 + 8] = ps1; g_ad2[r0 + 8] = pd1; }
    }
}

// -- fused layer-2 softmax+aggregate+bias+log_softmax (warp/dst, lane-par) ---
__global__ void __launch_bounds__(256) k_agg2(const float* __restrict__ b2,
                                              float* __restrict__ out, int n) {
    int d = (blockIdx.x * blockDim.x + threadIdx.x) >> 5;
    int lane = threadIdx.x & 31;
    if (d >= n) return;
    int beg = g_rowstart[d], end = g_rowstart[d + 1];
    float adv = __ldg(&g_ad2[d]);

    // phase 1: lane-parallel max over edges
    float mx = -3.4e38f;
    for (int i = beg + lane; i < end; i += 32) {
        float v = __ldg(&g_as2[__ldg(&g_col[i])]) + adv;
        v = (v > 0.f) ? v : NEG_SLOPE * v;
        mx = fmaxf(mx, v);
    }
    #pragma unroll
    for (int off = 16; off >= 1; off >>= 1)
        mx = fmaxf(mx, __shfl_xor_sync(0xffffffffu, mx, off));

    // phase 2: chunks of 32 edges; each lane owns one edge's alpha,
    // broadcast via shfl while all 32 lanes act as channels for the gather.
    float sum = 0.f, acc = 0.f;
    for (int base = beg; base < end; base += 32) {
        int i = base + lane;
        float myal = 0.f; int mycol = 0;
        if (i < end) {
            mycol = __ldg(&g_col[i]);
            float v = __ldg(&g_as2[mycol]) + adv;
            v = (v > 0.f) ? v : NEG_SLOPE * v;
            myal = __expf(v - mx);
        }
        sum += myal;
        int cnt = min(32, end - base);
        for (int j = 0; j < cnt; j++) {
            float al = __shfl_sync(0xffffffffu, myal, j);
            int s    = __shfl_sync(0xffffffffu, mycol, j);
            acc += __ldg(&g_h2[(size_t)s * 32 + lane]) * al;
        }
    }
    #pragma unroll
    for (int off = 16; off >= 1; off >>= 1)
        sum += __shfl_xor_sync(0xffffffffu, sum, off);

    float val = acc * (1.f / (sum + 1e-16f)) + b2[lane];
    float m2 = val;
    #pragma unroll
    for (int off = 16; off >= 1; off >>= 1)
        m2 = fmaxf(m2, __shfl_xor_sync(0xffffffffu, m2, off));
    float ex = __expf(val - m2);
    float s2 = ex;
    #pragma unroll
    for (int off = 16; off >= 1; off >>= 1)
        s2 += __shfl_xor_sync(0xffffffffu, s2, off);
    out[(size_t)d * 32 + lane] = val - m2 - logf(s2);
}

// ---------------- launch -----------------------------------------------------
extern "C" void kernel_launch(void* const* d_in, const int* in_sizes, int n_in,
                              void* d_out, int out_size) {
    const float* x    = (const float*)d_in[0];
    const int*   ei   = (const int*)d_in[1];
    const float* W1   = (const float*)d_in[2];
    const float* as1  = (const float*)d_in[3];
    const float* ad1  = (const float*)d_in[4];
    const float* b1   = (const float*)d_in[5];
    const float* W2   = (const float*)d_in[6];
    const float* as2  = (const float*)d_in[7];
    const float* ad2  = (const float*)d_in[8];
    const float* b2   = (const float*)d_in[9];
    float* out = (float*)d_out;

    int n = in_sizes[0] / FIN;
    int E = in_sizes[1] / 2;
    int etot = E + n;

    static cudaStream_t s2 = nullptr;
    static cudaEvent_t evFork = nullptr, evJoin = nullptr;
    if (!s2) {
        cudaStreamCreateWithFlags(&s2, cudaStreamNonBlocking);
        cudaEventCreateWithFlags(&evFork, cudaEventDisableTiming);
        cudaEventCreateWithFlags(&evJoin, cudaEventDisableTiming);
    }

    // fork: CSR build on side stream, overlapped with prep + GEMM1
    cudaEventRecord(evFork, 0);
    cudaStreamWaitEvent(s2, evFork, 0);
    k_deg_init<<<(n + 255) / 256, 256, 0, s2>>>(n);
    k_count<<<(E + 255) / 256, 256, 0, s2>>>(ei, E);
    k_scan<<<1, 1024, 0, s2>>>(n);
    k_scatter<<<(etot + 255) / 256, 256, 0, s2>>>(ei, E, etot);
    cudaEventRecord(evJoin, s2);

    // main stream: dense path
    k_prep_x<<<(n * 256 + 255) / 256, 256>>>(x, n * 256);
    k_prep_w<<<(256 * 256 + 255) / 256, 256>>>(W1);
    k_prep_w2<<<(32 * 256 + 255) / 256, 256>>>(W2);

    dim3 g1(2, (n + 127) / 128);
    k_gemm1_mma<<<g1, 256>>>(as1, ad1, n);

    // join: alpha/agg need the CSR
    cudaStreamWaitEvent(0, evJoin, 0);

    k_alpha1<<<(n + 255) / 256, 256>>>(n);
    k_agg1<<<n, 256>>>(b1);

    k_gemm2_mma<<<(n + 127) / 128, 256>>>(as2, ad2, n);
    k_agg2<<<(n * 32 + 255) / 256, 256>>>(b2, out, n);
}

// round 14
// speedup vs baseline: 1.5766x; 1.1232x over previous
#include <cuda_runtime.h>
#include <cuda_bf16.h>
#include <math.h>
#include <stdint.h>

#define NN    50000
#define EE    800000
#define FIN   256
#define ETOT  (EE + NN)
#define NEG_SLOPE 0.2f

// ---------------- scratch (device globals) ----------------------------------
__device__ __nv_bfloat16 g_h1[NN * 256];   // layer-1 linear output, bf16 [N,4,64]
__device__ float g_as1[NN * 4];
__device__ float g_ad1[NN * 4];
__device__ float g_h2[NN * 32];            // layer-2 linear output
__device__ float g_as2[NN];
__device__ float g_ad2[NN];
__device__ float g_alpha1[ETOT * 4];       // unnormalized exp weight per CSR slot, head
__device__ float g_rsum1[NN * 4];          // 1/(sum+eps) per (dst, head)
// split-bf16 operands for tensor-core GEMMs
__device__ __nv_bfloat16 g_w1hi[256 * 256];   // [n][k] (transposed W1)
__device__ __nv_bfloat16 g_w1lo[256 * 256];
__device__ __nv_bfloat16 g_a2hi[NN * 256];    // relu(agg1+b1) split
__device__ __nv_bfloat16 g_a2lo[NN * 256];
__device__ __nv_bfloat16 g_w2hi[32 * 256];    // [n][k] (transposed W2)
__device__ __nv_bfloat16 g_w2lo[32 * 256];
// CSR (dst-bucketed incoming edges; slot stores src node id)
__device__ int   g_deg[NN];
__device__ int   g_rowstart[NN + 1];
__device__ int   g_col[ETOT];

// ---------------- CSR build --------------------------------------------------
__global__ void k_deg_init(int n) {
    int i = blockIdx.x * blockDim.x + threadIdx.x;
    if (i < n) g_deg[i] = 1;
}
__global__ void k_count(const int* __restrict__ ei, int E) {
    int e = blockIdx.x * blockDim.x + threadIdx.x;
    if (e < E) atomicAdd(&g_deg[ei[E + e]], 1);
}
__global__ void k_scan(int n) {
    __shared__ int sh[1024];
    int tid = threadIdx.x;
    int chunk = (n + 1023) / 1024;
    int beg = tid * chunk;
    int end = min(beg + chunk, n);
    int s = 0;
    for (int i = beg; i < end; i++) s += g_deg[i];
    sh[tid] = s;
    __syncthreads();
    #pragma unroll
    for (int off = 1; off < 1024; off <<= 1) {
        int v = (tid >= off) ? sh[tid - off] : 0;
        __syncthreads();
        sh[tid] += v;
        __syncthreads();
    }
    int run = (tid == 0) ? 0 : sh[tid - 1];
    for (int i = beg; i < end; i++) {
        int c = g_deg[i];
        g_rowstart[i] = run;
        g_deg[i] = run;
        run += c;
    }
    if (tid == 0) g_rowstart[n] = sh[1023];
}
__global__ void k_scatter(const int* __restrict__ ei, int E, int etot) {
    int e = blockIdx.x * blockDim.x + threadIdx.x;
    if (e >= etot) return;
    int s, d;
    if (e < E) { s = ei[e]; d = ei[E + e]; }
    else       { s = d = e - E; }
    int pos = atomicAdd(&g_deg[d], 1);
    g_col[pos] = s;
}

// ---------------- split-bf16 weight prep (W1 + W2 in one kernel) ------------
__global__ void k_prep_w(const float* __restrict__ W1, const float* __restrict__ W2) {
    int i = blockIdx.x * blockDim.x + threadIdx.x;
    if (i < 256 * 256) {
        int n = i >> 8, k = i & 255;
        float f = W1[k * 256 + n];
        __nv_bfloat16 hi = __float2bfloat16_rn(f);
        g_w1hi[i] = hi;
        g_w1lo[i] = __float2bfloat16_rn(f - __bfloat162float(hi));
    } else if (i < 256 * 256 + 32 * 256) {
        int j = i - 256 * 256;
        int n = j >> 8, k = j & 255;
        float f = W2[k * 32 + n];
        __nv_bfloat16 hi = __float2bfloat16_rn(f);
        g_w2hi[j] = hi;
        g_w2lo[j] = __float2bfloat16_rn(f - __bfloat162float(hi));
    }
}

// ---------------- mma.sync helper -------------------------------------------
#define PAD_K 40          // 32 + 8 bf16 padding -> 80-byte rows (16B aligned)
__device__ __forceinline__ void mma16816(float* c, const uint32_t* a, const uint32_t* b) {
    asm volatile(
        "mma.sync.aligned.m16n8k16.row.col.f32.bf16.bf16.f32 "
        "{%0,%1,%2,%3}, {%4,%5,%6,%7}, {%8,%9}, {%0,%1,%2,%3};"
        : "+f"(c[0]), "+f"(c[1]), "+f"(c[2]), "+f"(c[3])
        : "r"(a[0]), "r"(a[1]), "r"(a[2]), "r"(a[3]), "r"(b[0]), "r"(b[1]));
}

// ------- GEMM1 via mma.sync bf16 (split hi/lo) + fused attn1 dots -----------
// A tiles converted fp32->hi/lo in-kernel (no prep_x pass).
// CTA tile 128x128, K chunks of 32; 8 warps (4 M x 2 N), warp tile 32x64.
// Epilogue: bf16 h1 store + per-head attention dots (fp32 accumulators).
__global__ void __launch_bounds__(256) k_gemm1_mma(const float* __restrict__ x,
                                                   const float* __restrict__ att_src,
                                                   const float* __restrict__ att_dst, int M) {
    __shared__ __nv_bfloat16 sAhi[128 * PAD_K];
    __shared__ __nv_bfloat16 sAlo[128 * PAD_K];
    __shared__ __nv_bfloat16 sBhi[128 * PAD_K];
    __shared__ __nv_bfloat16 sBlo[128 * PAD_K];

    int tid = threadIdx.x;
    int wid = tid >> 5, lane = tid & 31;
    int wm = wid >> 1, wn = wid & 1;          // 4 x 2 warps
    int row0 = blockIdx.y * 128;
    int col0 = blockIdx.x * 128;

    float acc[2][8][4] = {};

    int lq = lane & 3;
    int lr = lane >> 2;

    for (int kc = 0; kc < 256; kc += 32) {
        // A fill: fp32 x -> split bf16 (8 channels = 2 float4 loads per slot)
        #pragma unroll
        for (int i = 0; i < 2; i++) {
            int slot = tid + i * 256;
            int r = slot >> 2, q = slot & 3;
            int gr = row0 + r;
            __nv_bfloat16 hbuf[8], lbuf[8];
            if (gr < M) {
                const float* px = x + (size_t)gr * 256 + kc + q * 8;
                float4 f0 = *(const float4*)px;
                float4 f1 = *(const float4*)(px + 4);
                float fv[8] = {f0.x, f0.y, f0.z, f0.w, f1.x, f1.y, f1.z, f1.w};
                #pragma unroll
                for (int t = 0; t < 8; t++) {
                    __nv_bfloat16 hi = __float2bfloat16_rn(fv[t]);
                    hbuf[t] = hi;
                    lbuf[t] = __float2bfloat16_rn(fv[t] - __bfloat162float(hi));
                }
            } else {
                #pragma unroll
                for (int t = 0; t < 8; t++) { hbuf[t] = __float2bfloat16_rn(0.f); lbuf[t] = hbuf[t]; }
            }
            *(uint4*)(sAhi + r * PAD_K + q * 8) = *(uint4*)hbuf;
            *(uint4*)(sAlo + r * PAD_K + q * 8) = *(uint4*)lbuf;
        }
        #pragma unroll
        for (int i = 0; i < 2; i++) {
            int slot = tid + i * 256;
            int r = slot >> 2, q = slot & 3;
            int gn = col0 + r;
            *(uint4*)(sBhi + r * PAD_K + q * 8) = *(const uint4*)(g_w1hi + (size_t)gn * 256 + kc + q * 8);
            *(uint4*)(sBlo + r * PAD_K + q * 8) = *(const uint4*)(g_w1lo + (size_t)gn * 256 + kc + q * 8);
        }
        __syncthreads();

        #pragma unroll
        for (int ks = 0; ks < 2; ks++) {
            int kb = ks * 16;
            uint32_t ahi[2][4], alo[2][4], bhi[8][2], blo[8][2];
            #pragma unroll
            for (int mt = 0; mt < 2; mt++) {
                int rbase = wm * 32 + mt * 16;
                const __nv_bfloat16* p0h = sAhi + (rbase + lr) * PAD_K + kb + lq * 2;
                const __nv_bfloat16* p1h = sAhi + (rbase + 8 + lr) * PAD_K + kb + lq * 2;
                const __nv_bfloat16* p0l = sAlo + (rbase + lr) * PAD_K + kb + lq * 2;
                const __nv_bfloat16* p1l = sAlo + (rbase + 8 + lr) * PAD_K + kb + lq * 2;
                ahi[mt][0] = *(const uint32_t*)p0h;
                ahi[mt][1] = *(const uint32_t*)p1h;
                ahi[mt][2] = *(const uint32_t*)(p0h + 8);
                ahi[mt][3] = *(const uint32_t*)(p1h + 8);
                alo[mt][0] = *(const uint32_t*)p0l;
                alo[mt][1] = *(const uint32_t*)p1l;
                alo[mt][2] = *(const uint32_t*)(p0l + 8);
                alo[mt][3] = *(const uint32_t*)(p1l + 8);
            }
            #pragma unroll
            for (int nt = 0; nt < 8; nt++) {
                int nbase = wn * 64 + nt * 8;
                const __nv_bfloat16* ph = sBhi + (nbase + lr) * PAD_K + kb + lq * 2;
                const __nv_bfloat16* pl = sBlo + (nbase + lr) * PAD_K + kb + lq * 2;
                bhi[nt][0] = *(const uint32_t*)ph;
                bhi[nt][1] = *(const uint32_t*)(ph + 8);
                blo[nt][0] = *(const uint32_t*)pl;
                blo[nt][1] = *(const uint32_t*)(pl + 8);
            }
            #pragma unroll
            for (int mt = 0; mt < 2; mt++)
                #pragma unroll
                for (int nt = 0; nt < 8; nt++) {
                    mma16816(acc[mt][nt], ahi[mt], bhi[nt]);
                    mma16816(acc[mt][nt], ahi[mt], blo[nt]);
                    mma16816(acc[mt][nt], alo[mt], bhi[nt]);
                }
        }
        __syncthreads();
    }

    int h = (col0 >> 6) + wn;   // this warp's head
    #pragma unroll
    for (int mt = 0; mt < 2; mt++) {
        int r0 = row0 + wm * 32 + mt * 16 + lr;
        float ps0 = 0.f, pd0 = 0.f, ps1 = 0.f, pd1 = 0.f;
        #pragma unroll
        for (int nt = 0; nt < 8; nt++) {
            int c = col0 + wn * 64 + nt * 8 + lq * 2;
            int ci = h * 64 + nt * 8 + lq * 2;
            float a0 = __ldg(&att_src[ci]), a1 = __ldg(&att_src[ci + 1]);
            float d0 = __ldg(&att_dst[ci]), d1 = __ldg(&att_dst[ci + 1]);
            ps0 += acc[mt][nt][0] * a0 + acc[mt][nt][1] * a1;
            pd0 += acc[mt][nt][0] * d0 + acc[mt][nt][1] * d1;
            ps1 += acc[mt][nt][2] * a0 + acc[mt][nt][3] * a1;
            pd1 += acc[mt][nt][2] * d0 + acc[mt][nt][3] * d1;
            if (r0 < M)
                *(__nv_bfloat162*)(g_h1 + (size_t)r0 * 256 + c) =
                    __float22bfloat162_rn(make_float2(acc[mt][nt][0], acc[mt][nt][1]));
            if (r0 + 8 < M)
                *(__nv_bfloat162*)(g_h1 + (size_t)(r0 + 8) * 256 + c) =
                    __float22bfloat162_rn(make_float2(acc[mt][nt][2], acc[mt][nt][3]));
        }
        #pragma unroll
        for (int off = 1; off <= 2; off <<= 1) {
            ps0 += __shfl_xor_sync(0xffffffffu, ps0, off);
            pd0 += __shfl_xor_sync(0xffffffffu, pd0, off);
            ps1 += __shfl_xor_sync(0xffffffffu, ps1, off);
            pd1 += __shfl_xor_sync(0xffffffffu, pd1, off);
        }
        if (lq == 0) {
            if (r0 < M)     { g_as1[r0 * 4 + h] = ps0;       g_ad1[r0 * 4 + h] = pd0; }
            if (r0 + 8 < M) { g_as1[(r0 + 8) * 4 + h] = ps1; g_ad1[(r0 + 8) * 4 + h] = pd1; }
        }
    }
}

// ------ alpha precompute, layer 1 (thread per dst; all 4 heads, float4) -----
__global__ void k_alpha1(int n) {
    int d = blockIdx.x * blockDim.x + threadIdx.x;
    if (d >= n) return;
    int beg = g_rowstart[d], end = g_rowstart[d + 1];
    float4 adv = *(const float4*)&g_ad1[d * 4];
    float4 mx = make_float4(-3.4e38f, -3.4e38f, -3.4e38f, -3.4e38f);
    for (int i = beg; i < end; i++) {
        float4 a = __ldg((const float4*)&g_as1[__ldg(&g_col[i]) * 4]);
        float vx = a.x + adv.x, vy = a.y + adv.y, vz = a.z + adv.z, vw = a.w + adv.w;
        vx = (vx > 0.f) ? vx : NEG_SLOPE * vx;
        vy = (vy > 0.f) ? vy : NEG_SLOPE * vy;
        vz = (vz > 0.f) ? vz : NEG_SLOPE * vz;
        vw = (vw > 0.f) ? vw : NEG_SLOPE * vw;
        mx.x = fmaxf(mx.x, vx); mx.y = fmaxf(mx.y, vy);
        mx.z = fmaxf(mx.z, vz); mx.w = fmaxf(mx.w, vw);
    }
    float4 sum = make_float4(0.f, 0.f, 0.f, 0.f);
    for (int i = beg; i < end; i++) {
        float4 a = __ldg((const float4*)&g_as1[__ldg(&g_col[i]) * 4]);
        float vx = a.x + adv.x, vy = a.y + adv.y, vz = a.z + adv.z, vw = a.w + adv.w;
        vx = (vx > 0.f) ? vx : NEG_SLOPE * vx;
        vy = (vy > 0.f) ? vy : NEG_SLOPE * vy;
        vz = (vz > 0.f) ? vz : NEG_SLOPE * vz;
        vw = (vw > 0.f) ? vw : NEG_SLOPE * vw;
        float4 ex = make_float4(__expf(vx - mx.x), __expf(vy - mx.y),
                                __expf(vz - mx.z), __expf(vw - mx.w));
        *(float4*)&g_alpha1[i * 4] = ex;
        sum.x += ex.x; sum.y += ex.y; sum.z += ex.z; sum.w += ex.w;
    }
    *(float4*)&g_rsum1[d * 4] = make_float4(
        1.f / (sum.x + 1e-16f), 1.f / (sum.y + 1e-16f),
        1.f / (sum.z + 1e-16f), 1.f / (sum.w + 1e-16f));
}

// --- fused layer-1 aggregate + bias + relu -> split bf16 ---------------------
// 128 threads per dst; each thread owns 2 channels via one bf16x2 load/edge.
__global__ void __launch_bounds__(128) k_agg1(const float* __restrict__ b1) {
    int d = blockIdx.x;
    int tid = threadIdx.x;              // channel pair index 0..127
    int h = tid >> 5;                   // 32 pairs per head
    int beg = g_rowstart[d], end = g_rowstart[d + 1];
    float acc0 = 0.f, acc1 = 0.f;
    int i = beg;
    for (; i + 1 < end; i += 2) {
        int s0 = __ldg(&g_col[i]);
        int s1 = __ldg(&g_col[i + 1]);
        float w0 = __ldg(&g_alpha1[i * 4 + h]);
        float w1 = __ldg(&g_alpha1[(i + 1) * 4 + h]);
        float2 v0 = __bfloat1622float2(*(const __nv_bfloat162*)(g_h1 + (size_t)s0 * 256 + tid * 2));
        float2 v1 = __bfloat1622float2(*(const __nv_bfloat162*)(g_h1 + (size_t)s1 * 256 + tid * 2));
        acc0 += v0.x * w0 + v1.x * w1;
        acc1 += v0.y * w0 + v1.y * w1;
    }
    if (i < end) {
        int s0 = __ldg(&g_col[i]);
        float w0 = __ldg(&g_alpha1[i * 4 + h]);
        float2 v0 = __bfloat1622float2(*(const __nv_bfloat162*)(g_h1 + (size_t)s0 * 256 + tid * 2));
        acc0 += v0.x * w0;
        acc1 += v0.y * w0;
    }
    float rs = g_rsum1[d * 4 + h];
    float val0 = fmaxf(acc0 * rs + b1[tid * 2], 0.f);
    float val1 = fmaxf(acc1 * rs + b1[tid * 2 + 1], 0.f);
    __nv_bfloat16 hi0 = __float2bfloat16_rn(val0);
    __nv_bfloat16 hi1 = __float2bfloat16_rn(val1);
    __nv_bfloat162 hp; hp.x = hi0; hp.y = hi1;
    __nv_bfloat162 lp;
    lp.x = __float2bfloat16_rn(val0 - __bfloat162float(hi0));
    lp.y = __float2bfloat16_rn(val1 - __bfloat162float(hi1));
    *(__nv_bfloat162*)(g_a2hi + (size_t)d * 256 + tid * 2) = hp;
    *(__nv_bfloat162*)(g_a2lo + (size_t)d * 256 + tid * 2) = lp;
}

// ------- GEMM2 via mma.sync bf16 (split hi/lo) + fused attn2 dots -----------
// CTA tile 128x32, 8 warps (8 M x 1 N), warp tile 16x32; K chunks of 32.
__global__ void __launch_bounds__(256) k_gemm2_mma(const float* __restrict__ att_src,
                                                   const float* __restrict__ att_dst, int M) {
    __shared__ __nv_bfloat16 sAhi[128 * PAD_K];
    __shared__ __nv_bfloat16 sAlo[128 * PAD_K];
    __shared__ __nv_bfloat16 sBhi[32 * PAD_K];
    __shared__ __nv_bfloat16 sBlo[32 * PAD_K];

    int tid = threadIdx.x;
    int wid = tid >> 5, lane = tid & 31;
    int row0 = blockIdx.x * 128;
    int lq = lane & 3;
    int lr = lane >> 2;

    float acc[4][4] = {};

    for (int kc = 0; kc < 256; kc += 32) {
        #pragma unroll
        for (int i = 0; i < 2; i++) {
            int slot = tid + i * 256;
            int r = slot >> 2, q = slot & 3;
            int gr = row0 + r;
            uint4 vh = make_uint4(0, 0, 0, 0), vl = make_uint4(0, 0, 0, 0);
            if (gr < M) {
                vh = *(const uint4*)(g_a2hi + (size_t)gr * 256 + kc + q * 8);
                vl = *(const uint4*)(g_a2lo + (size_t)gr * 256 + kc + q * 8);
            }
            *(uint4*)(sAhi + r * PAD_K + q * 8) = vh;
            *(uint4*)(sAlo + r * PAD_K + q * 8) = vl;
        }
        if (tid < 128) {
            int r = tid >> 2, q = tid & 3;
            *(uint4*)(sBhi + r * PAD_K + q * 8) = *(const uint4*)(g_w2hi + (size_t)r * 256 + kc + q * 8);
            *(uint4*)(sBlo + r * PAD_K + q * 8) = *(const uint4*)(g_w2lo + (size_t)r * 256 + kc + q * 8);
        }
        __syncthreads();

        #pragma unroll
        for (int ks = 0; ks < 2; ks++) {
            int kb = ks * 16;
            uint32_t ahi[4], alo[4], bhi[4][2], blo[4][2];
            int rbase = wid * 16;
            const __nv_bfloat16* p0h = sAhi + (rbase + lr) * PAD_K + kb + lq * 2;
            const __nv_bfloat16* p1h = sAhi + (rbase + 8 + lr) * PAD_K + kb + lq * 2;
            const __nv_bfloat16* p0l = sAlo + (rbase + lr) * PAD_K + kb + lq * 2;
            const __nv_bfloat16* p1l = sAlo + (rbase + 8 + lr) * PAD_K + kb + lq * 2;
            ahi[0] = *(const uint32_t*)p0h;
            ahi[1] = *(const uint32_t*)p1h;
            ahi[2] = *(const uint32_t*)(p0h + 8);
            ahi[3] = *(const uint32_t*)(p1h + 8);
            alo[0] = *(const uint32_t*)p0l;
            alo[1] = *(const uint32_t*)p1l;
            alo[2] = *(const uint32_t*)(p0l + 8);
            alo[3] = *(const uint32_t*)(p1l + 8);
            #pragma unroll
            for (int nt = 0; nt < 4; nt++) {
                int nbase = nt * 8;
                const __nv_bfloat16* ph = sBhi + (nbase + lr) * PAD_K + kb + lq * 2;
                const __nv_bfloat16* pl = sBlo + (nbase + lr) * PAD_K + kb + lq * 2;
                bhi[nt][0] = *(const uint32_t*)ph;
                bhi[nt][1] = *(const uint32_t*)(ph + 8);
                blo[nt][0] = *(const uint32_t*)pl;
                blo[nt][1] = *(const uint32_t*)(pl + 8);
            }
            #pragma unroll
            for (int nt = 0; nt < 4; nt++) {
                mma16816(acc[nt], ahi, bhi[nt]);
                mma16816(acc[nt], ahi, blo[nt]);
                mma16816(acc[nt], alo, bhi[nt]);
            }
        }
        __syncthreads();
    }

    int r0 = row0 + wid * 16 + lr;
    float ps0 = 0.f, pd0 = 0.f, ps1 = 0.f, pd1 = 0.f;
    #pragma unroll
    for (int nt = 0; nt < 4; nt++) {
        int c = nt * 8 + lq * 2;
        float a0 = __ldg(&att_src[c]), a1 = __ldg(&att_src[c + 1]);
        float d0 = __ldg(&att_dst[c]), d1 = __ldg(&att_dst[c + 1]);
        ps0 += acc[nt][0] * a0 + acc[nt][1] * a1;
        pd0 += acc[nt][0] * d0 + acc[nt][1] * d1;
        ps1 += acc[nt][2] * a0 + acc[nt][3] * a1;
        pd1 += acc[nt][2] * d0 + acc[nt][3] * d1;
        if (r0 < M)
            *(float2*)(g_h2 + (size_t)r0 * 32 + c) = make_float2(acc[nt][0], acc[nt][1]);
        if (r0 + 8 < M)
            *(float2*)(g_h2 + (size_t)(r0 + 8) * 32 + c) = make_float2(acc[nt][2], acc[nt][3]);
    }
    #pragma unroll
    for (int off = 1; off <= 2; off <<= 1) {
        ps0 += __shfl_xor_sync(0xffffffffu, ps0, off);
        pd0 += __shfl_xor_sync(0xffffffffu, pd0, off);
        ps1 += __shfl_xor_sync(0xffffffffu, ps1, off);
        pd1 += __shfl_xor_sync(0xffffffffu, pd1, off);
    }
    if (lq == 0) {
        if (r0 < M)     { g_as2[r0] = ps0;     g_ad2[r0] = pd0; }
        if (r0 + 8 < M) { g_as2[r0 + 8] = ps1; g_ad2[r0 + 8] = pd1; }
    }
}

// -- fused layer-2 softmax+aggregate+bias+log_softmax (warp/dst, lane-par) ---
__global__ void __launch_bounds__(256) k_agg2(const float* __restrict__ b2,
                                              float* __restrict__ out, int n) {
    int d = (blockIdx.x * blockDim.x + threadIdx.x) >> 5;
    int lane = threadIdx.x & 31;
    if (d >= n) return;
    int beg = g_rowstart[d], end = g_rowstart[d + 1];
    float adv = __ldg(&g_ad2[d]);

    float mx = -3.4e38f;
    for (int i = beg + lane; i < end; i += 32) {
        float v = __ldg(&g_as2[__ldg(&g_col[i])]) + adv;
        v = (v > 0.f) ? v : NEG_SLOPE * v;
        mx = fmaxf(mx, v);
    }
    #pragma unroll
    for (int off = 16; off >= 1; off >>= 1)
        mx = fmaxf(mx, __shfl_xor_sync(0xffffffffu, mx, off));

    float sum = 0.f, acc = 0.f;
    for (int base = beg; base < end; base += 32) {
        int i = base + lane;
        float myal = 0.f; int mycol = 0;
        if (i < end) {
            mycol = __ldg(&g_col[i]);
            float v = __ldg(&g_as2[mycol]) + adv;
            v = (v > 0.f) ? v : NEG_SLOPE * v;
            myal = __expf(v - mx);
        }
        sum += myal;
        int cnt = min(32, end - base);
        for (int j = 0; j < cnt; j++) {
            float al = __shfl_sync(0xffffffffu, myal, j);
            int s    = __shfl_sync(0xffffffffu, mycol, j);
            acc += __ldg(&g_h2[(size_t)s * 32 + lane]) * al;
        }
    }
    #pragma unroll
    for (int off = 16; off >= 1; off >>= 1)
        sum += __shfl_xor_sync(0xffffffffu, sum, off);

    float val = acc * (1.f / (sum + 1e-16f)) + b2[lane];
    float m2 = val;
    #pragma unroll
    for (int off = 16; off >= 1; off >>= 1)
        m2 = fmaxf(m2, __shfl_xor_sync(0xffffffffu, m2, off));
    float ex = __expf(val - m2);
    float s2 = ex;
    #pragma unroll
    for (int off = 16; off >= 1; off >>= 1)
        s2 += __shfl_xor_sync(0xffffffffu, s2, off);
    out[(size_t)d * 32 + lane] = val - m2 - logf(s2);
}

// ---------------- launch -----------------------------------------------------
extern "C" void kernel_launch(void* const* d_in, const int* in_sizes, int n_in,
                              void* d_out, int out_size) {
    const float* x    = (const float*)d_in[0];
    const int*   ei   = (const int*)d_in[1];
    const float* W1   = (const float*)d_in[2];
    const float* as1  = (const float*)d_in[3];
    const float* ad1  = (const float*)d_in[4];
    const float* b1   = (const float*)d_in[5];
    const float* W2   = (const float*)d_in[6];
    const float* as2  = (const float*)d_in[7];
    const float* ad2  = (const float*)d_in[8];
    const float* b2   = (const float*)d_in[9];
    float* out = (float*)d_out;

    int n = in_sizes[0] / FIN;
    int E = in_sizes[1] / 2;
    int etot = E + n;

    static cudaStream_t s2 = nullptr;
    static cudaEvent_t evFork = nullptr, evJoin = nullptr;
    if (!s2) {
        cudaStreamCreateWithFlags(&s2, cudaStreamNonBlocking);
        cudaEventCreateWithFlags(&evFork, cudaEventDisableTiming);
        cudaEventCreateWithFlags(&evJoin, cudaEventDisableTiming);
    }

    // fork: CSR build on side stream, overlapped with prep + GEMM1
    cudaEventRecord(evFork, 0);
    cudaStreamWaitEvent(s2, evFork, 0);
    k_deg_init<<<(n + 255) / 256, 256, 0, s2>>>(n);
    k_count<<<(E + 255) / 256, 256, 0, s2>>>(ei, E);
    k_scan<<<1, 1024, 0, s2>>>(n);
    k_scatter<<<(etot + 255) / 256, 256, 0, s2>>>(ei, E, etot);
    cudaEventRecord(evJoin, s2);

    // main stream: dense path
    k_prep_w<<<(256 * 256 + 32 * 256 + 255) / 256, 256>>>(W1, W2);

    dim3 g1(2, (n + 127) / 128);
    k_gemm1_mma<<<g1, 256>>>(x, as1, ad1, n);

    // join: alpha/agg need the CSR
    cudaStreamWaitEvent(0, evJoin, 0);

    k_alpha1<<<(n + 255) / 256, 256>>>(n);
    k_agg1<<<n, 128>>>(b1);

    k_gemm2_mma<<<(n + 127) / 128, 256>>>(as2, ad2, n);
    k_agg2<<<(n * 32 + 255) / 256, 256>>>(b2, out, n);
}